// round 11
// baseline (speedup 1.0000x reference)
#include <cuda_runtime.h>

#define B_ 8
#define P_ 57744
#define C_ 81
#define N_ 20
#define ROWS_ (B_ * P_)
#define POS_TH 0.5f
#define NEG_TH 0.4f
#define CAND_CAP 131072
#define SM_CAND 2048

// ---------------- scratch (static __device__, zero-init at load) -------------
// Pipeline is self-cleaning: k_ce resets everything for the next replay.
__device__ unsigned char      g_mt[ROWS_];      // (gt_idx<<2)|band; band3=forced
__device__ unsigned long long g_gt_best[B_ * N_];   // k_ce pre-seeds fallback
__device__ unsigned long long g_keys[ROWS_];
__device__ signed char        g_conf[ROWS_];
__device__ int                g_hist0[2048];
__device__ int                g_hist1[2048];
__device__ unsigned long long g_cand[CAND_CAP];
__device__ int                g_cand_cnt;
__device__ int                g_work[ROWS_];    // (r<<8) | target
__device__ int                g_work_cnt;
__device__ int                g_num_pos;
__device__ int                g_K;
__device__ int                g_d1;
__device__ long long          g_Krem1;
__device__ float              g_sl1;
__device__ float              g_ce_sum;
__device__ int                g_done_match;
__device__ int                g_done_conf;
__device__ int                g_done_s1;
__device__ int                g_done_ce;
__device__ int                g_seeded;         // 0 on first run: seed gt_best

__device__ __forceinline__ float smooth_l1(float d) {
    float ad = fabsf(d);
    return ad < 1.f ? 0.5f * d * d : ad - 0.5f;
}
__device__ __forceinline__ unsigned ord_bits(float x) {
    unsigned b = __float_as_uint(x);
    unsigned m = (unsigned)((int)b >> 31) | 0x80000000u;
    return b ^ m;   // monotonic float -> uint
}

// warp-aggregated append (call from ALL lanes, uniform control flow)
__device__ __forceinline__ int warp_append(int* ctr, bool pred) {
    unsigned bal = __ballot_sync(0xffffffffu, pred);
    int lane = threadIdx.x & 31;
    int base = 0;
    int leader = __ffs(bal) - 1;
    if (bal && lane == leader) base = atomicAdd(ctr, __popc(bal));
    base = __shfl_sync(0xffffffffu, base, leader < 0 ? 0 : leader);
    return base + __popc(bal & ((1u << lane) - 1u));
}

// suffix-scan pick over 2048 buckets, 256 threads.
__device__ void pick_digit(const int* hist, long long Krem_in,
                           int& d_out, long long& Krem_out) {
    __shared__ long long suf[256];
    __shared__ int s_d;
    __shared__ long long s_k;
    int t = threadIdx.x;
    int h[8];
    long long s = 0;
    #pragma unroll
    for (int i = 0; i < 8; i++) { h[i] = hist[t * 8 + i]; s += h[i]; }
    suf[t] = s;
    __syncthreads();
    #pragma unroll
    for (int off = 1; off < 256; off <<= 1) {
        long long v = (t + off < 256) ? suf[t + off] : 0;
        __syncthreads();
        suf[t] += v;
        __syncthreads();
    }
    long long above = (t + 1 < 256) ? suf[t + 1] : 0;
    if (suf[t] >= Krem_in && above < Krem_in) {
        long long ab = above;
        int d = t * 8;
        #pragma unroll
        for (int i = 7; i >= 0; i--) {
            if (ab + h[i] >= Krem_in) { d = t * 8 + i; break; }
            ab += h[i];
        }
        s_d = d; s_k = Krem_in - ab;
    }
    __syncthreads();
    d_out = s_d;
    Krem_out = s_k;
}

// ---------------- K1: matching + (last block) force-patch --------------------
__global__ void k_match(const float* __restrict__ priors,
                        const float* __restrict__ gt_boxes) {
    int b = blockIdx.y;
    int p = blockIdx.x * 256 + threadIdx.x;

    __shared__ float4 s_gt[N_];
    __shared__ float  s_area[N_];
    __shared__ unsigned long long s_best[N_];
    // first-ever run: g_gt_best is zero-init; seed fallback keys once
    if (blockIdx.x == 0 && blockIdx.y == 0 && threadIdx.x == 0) {
        if (atomicExch(&g_seeded, 1) == 0) {
            for (int i = 0; i < B_ * N_; i++)
                atomicMax(&g_gt_best[i], 0x00000000FFFFFFFFull);
        }
    }
    if (threadIdx.x < N_) {
        float4 g = reinterpret_cast<const float4*>(gt_boxes)[b * N_ + threadIdx.x];
        s_gt[threadIdx.x] = g;
        s_area[threadIdx.x] = (g.z - g.x) * (g.w - g.y);
        s_best[threadIdx.x] = 0x00000000FFFFFFFFull;  // fallback prior 0
    }
    __syncthreads();

    if (p < P_) {
        float4 pr = reinterpret_cast<const float4*>(priors)[p];
        float px1 = pr.x - pr.z * 0.5f, py1 = pr.y - pr.w * 0.5f;
        float px2 = pr.x + pr.z * 0.5f, py2 = pr.y + pr.w * 0.5f;
        float parea = (px2 - px1) * (py2 - py1);

        float best = 0.f; int bestn = 0;
        #pragma unroll
        for (int n = 0; n < N_; n++) {
            float4 g = s_gt[n];
            float ix1 = fmaxf(px1, g.x), iy1 = fmaxf(py1, g.y);
            float ix2 = fminf(px2, g.z), iy2 = fminf(py2, g.w);
            float iw = fmaxf(ix2 - ix1, 0.f), ih = fmaxf(iy2 - iy1, 0.f);
            float inter = iw * ih;
            float iou = inter / (s_area[n] + parea - inter);
            if (iou > best) { best = iou; bestn = n; }
            if (inter > 0.f) {
                unsigned long long key =
                    (((unsigned long long)__float_as_uint(iou)) << 32) |
                    (unsigned)(~(unsigned)p);
                atomicMax(&s_best[n], key);
            }
        }
        int band = (best < NEG_TH) ? 0 : ((best < POS_TH) ? 1 : 2);
        g_mt[b * P_ + p] = (unsigned char)((bestn << 2) | band);
    }
    __syncthreads();
    if (threadIdx.x < N_)
        atomicMax(&g_gt_best[b * N_ + threadIdx.x], s_best[threadIdx.x]);

    // last block patches forced matches into g_mt (band 3, last-GT-wins)
    __shared__ int s_last;
    __threadfence();
    __syncthreads();
    if (threadIdx.x == 0)
        s_last = (atomicAdd(&g_done_match, 1) ==
                  (int)(gridDim.x * gridDim.y) - 1);
    __syncthreads();
    if (!s_last) return;
    int w  = threadIdx.x >> 5;    // 8 warps = 8 batches
    int ln = threadIdx.x & 31;
    if (ln < N_) {
        unsigned long long key = g_gt_best[w * N_ + ln];
        unsigned p2 = ~(unsigned)(key & 0xFFFFFFFFull);
        unsigned msk = __match_any_sync(0xFFFFFu, p2);
        int winner = 31 - __clz((int)msk);   // highest n among dup priors
        if (ln == winner)
            g_mt[w * P_ + p2] = (unsigned char)((ln << 2) | 3);
    }
}

// ---------------- K2: conf scan + loc loss + hist0 + pick d1 -----------------
__global__ void __launch_bounds__(256, 5)
k_conf(const float* __restrict__ conf_data,
       const float* __restrict__ loc_data,
       const float* __restrict__ priors,
       const float* __restrict__ gt_boxes,
       const int* __restrict__ gt_labels) {
    const float NINF = __int_as_float(0xff800000);
    __shared__ int s_hist[2048];
    __shared__ int s_labels[B_ * N_];
    for (int i = threadIdx.x; i < 2048; i += 256) s_hist[i] = 0;
    if (threadIdx.x < B_ * N_) s_labels[threadIdx.x] = gt_labels[threadIdx.x];
    __syncthreads();

    const int lane = threadIdx.x & 31;
    const int wid  = (blockIdx.x * blockDim.x + threadIdx.x) >> 5;
    const int nw   = (gridDim.x * blockDim.x) >> 5;

    float lsl = 0.f;
    const int NCH = ROWS_ / 8;
    const unsigned long long* mtp =
        reinterpret_cast<const unsigned long long*>(g_mt);

    for (int ch = wid; ch < NCH; ch += nw) {
        int r0 = ch * 8;
        unsigned long long mt8 = __ldg(mtp + ch);
        const float* base = conf_data + (size_t)r0 * C_;
        float fr[8];
        #pragma unroll
        for (int j = 0; j < 8; j++) {
            const float* row = base + j * C_;
            float a  = __ldcs(row + lane);
            float b2 = __ldcs(row + lane + 32);
            float c2 = (lane < 17) ? __ldcs(row + lane + 64) : NINF;
            fr[j] = fmaxf(fmaxf(lane ? a : NINF, b2), c2);
        }
        unsigned mr[8];
        #pragma unroll
        for (int j = 0; j < 8; j++)
            mr[j] = __reduce_max_sync(0xffffffffu, ord_bits(fr[j]));

        if (lane < 8) {
            unsigned uu = (lane & 4)
                ? ((lane & 2) ? ((lane & 1) ? mr[7] : mr[6])
                              : ((lane & 1) ? mr[5] : mr[4]))
                : ((lane & 2) ? ((lane & 1) ? mr[3] : mr[2])
                              : ((lane & 1) ? mr[1] : mr[0]));
            int r = r0 + lane;
            int b = r / P_;
            int p = r - b * P_;
            unsigned mt = (unsigned)((mt8 >> (lane * 8)) & 0xFF);
            int band = mt & 3;
            int n = mt >> 2;
            int c = (band == 0) ? 0 : ((band == 1) ? -1 : s_labels[b * N_ + n]);
            g_conf[r] = (signed char)c;
            unsigned u = (c == 0) ? uu : 0u;
            unsigned long long key =
                (((unsigned long long)u) << 32) | (unsigned)(~(unsigned)r);
            g_keys[r] = key;
            atomicAdd(&s_hist[(int)(key >> 53)], 1);
            if (c > 0) {
                float4 pr = reinterpret_cast<const float4*>(priors)[p];
                float4 g  = reinterpret_cast<const float4*>(gt_boxes)[b * N_ + n];
                float4 ld = reinterpret_cast<const float4*>(loc_data)[r];
                float tx = ((g.x + g.z) * 0.5f - pr.x) / (0.1f * pr.z);
                float ty = ((g.y + g.w) * 0.5f - pr.y) / (0.1f * pr.w);
                float tw = logf((g.z - g.x) / pr.z) * 5.0f;
                float th = logf((g.w - g.y) / pr.w) * 5.0f;
                lsl += smooth_l1(ld.x - tx) + smooth_l1(ld.y - ty)
                     + smooth_l1(ld.z - tw) + smooth_l1(ld.w - th);
                int pos = atomicAdd(&g_work_cnt, 1);   // ~700 total: cheap
                g_work[pos] = (r << 8) | c;
            }
        }
    }

    #pragma unroll
    for (int o = 16; o; o >>= 1) lsl += __shfl_xor_sync(0xffffffffu, lsl, o);
    __shared__ float sf[8];
    int w = threadIdx.x >> 5;
    if (lane == 0) sf[w] = lsl;
    __syncthreads();
    if (threadIdx.x == 0) {
        float a = 0.f;
        #pragma unroll
        for (int i = 0; i < 8; i++) a += sf[i];
        if (a != 0.f) atomicAdd(&g_sl1, a);
    }
    __syncthreads();
    for (int i = threadIdx.x; i < 2048; i += 256) {
        int v = s_hist[i];
        if (v) atomicAdd(&g_hist0[i], v);
    }

    // last block: num_pos from worklist (all entries are positives), pick d1
    __shared__ int s_last;
    __threadfence();
    if (threadIdx.x == 0)
        s_last = (atomicAdd(&g_done_conf, 1) == (int)gridDim.x - 1);
    __syncthreads();
    if (!s_last) return;
    int np = g_work_cnt;
    long long K = 3LL * np;
    if (K > ROWS_) K = ROWS_;
    if (threadIdx.x == 0) { g_num_pos = np; g_K = (int)K; }
    if (K == 0) return;
    int d1; long long kr;
    pick_digit(g_hist0, K, d1, kr);
    if (threadIdx.x == 0) { g_d1 = d1; g_Krem1 = kr; }
}

// ---------------- K3: key scan + hist1; last block: full select resolve ------
__global__ void __launch_bounds__(256) k_scan1() {
    if (g_K == 0) return;
    const unsigned long long D1 = (unsigned long long)g_d1;
    __shared__ int sh[2048];
    for (int i = threadIdx.x; i < 2048; i += 256) sh[i] = 0;
    __syncthreads();

    int i = blockIdx.x * 256 + threadIdx.x;
    bool in = (i < ROWS_ / 2);
    ulonglong2 kk = in ? reinterpret_cast<const ulonglong2*>(g_keys)[i]
                       : make_ulonglong2(0, 0);
    #pragma unroll
    for (int j = 0; j < 2; j++) {
        unsigned long long key = j ? kk.y : kk.x;
        unsigned long long d = key >> 53;
        bool is_cand = in && (d == D1);
        bool is_keep = in && (d > D1);
        if (is_cand) atomicAdd(&sh[(int)((key >> 42) & 2047)], 1);
        int cslot = warp_append(&g_cand_cnt, is_cand);
        if (is_cand && cslot < CAND_CAP) g_cand[cslot] = key;
        int kslot = warp_append(&g_work_cnt, is_keep);
        if (is_keep)
            g_work[kslot] = ((int)(~(unsigned)(key & 0xFFFFFFFFull))) << 8;
    }
    __syncthreads();
    for (int i2 = threadIdx.x; i2 < 2048; i2 += 256) {
        int v = sh[i2];
        if (v) atomicAdd(&g_hist1[i2], v);
    }

    // last block: pick d2, process cand buffer, exact 42-bit resolve
    __shared__ int s_last;
    __threadfence();
    if (threadIdx.x == 0)
        s_last = (atomicAdd(&g_done_s1, 1) == (int)gridDim.x - 1);
    __syncthreads();
    if (!s_last) return;

    int d2; long long Krem2;
    pick_digit(g_hist1, g_Krem1, d2, Krem2);
    const unsigned long long D2 = (unsigned long long)d2;

    __shared__ unsigned long long s_cand[SM_CAND];
    __shared__ int s_c2;
    if (threadIdx.x == 0) s_c2 = 0;
    __syncthreads();

    int cnt = g_cand_cnt;
    if (cnt > CAND_CAP) cnt = CAND_CAP;
    // scan cand buffer: mid>d2 -> keep (bg rows); mid==d2 -> tie set
    int iters = (cnt + 255) / 256;
    for (int it = 0; it < iters; it++) {
        int idx = it * 256 + threadIdx.x;
        bool in2 = (idx < cnt);
        unsigned long long key = in2 ? g_cand[idx] : 0ull;
        unsigned long long mid = (key >> 42) & 2047;
        bool is_tie = in2 && (mid == D2);
        bool pre    = in2 && (mid > D2);
        int r = pre ? (int)(~(unsigned)(key & 0xFFFFFFFFull)) : 0;
        bool is_keep = pre && (g_conf[r] == 0);
        int cslot = warp_append(&s_c2, is_tie);
        if (is_tie && cslot < SM_CAND) s_cand[cslot] = key;
        int kslot = warp_append(&g_work_cnt, is_keep);
        if (is_keep) g_work[kslot] = r << 8;
    }
    __syncthreads();
    int c2 = s_c2;
    if (c2 > SM_CAND) c2 = SM_CAND;
    if (threadIdx.x >= 32) return;

    int lane = threadIdx.x;
    unsigned long long F = (D1 << 11) | D2;
    long long Kr = Krem2;
    for (int b = 41; b >= 0; b--) {
        int local = 0;
        for (int i3 = lane; i3 < c2; i3 += 32) {
            unsigned long long k2 = s_cand[i3];
            if ((k2 >> (b + 1)) == F && ((k2 >> b) & 1ull)) local++;
        }
        int c1 = __reduce_add_sync(0xffffffffu, local);
        if (c1 >= Kr) F = (F << 1) | 1ull;
        else { Kr -= c1; F <<= 1; }
    }
    for (int i3 = lane; i3 < c2; i3 += 32) {
        unsigned long long k2 = s_cand[i3];
        if (k2 >= F) {
            int r = (int)(~(unsigned)(k2 & 0xFFFFFFFFull));
            if (g_conf[r] == 0) {
                int pos = atomicAdd(&g_work_cnt, 1);
                g_work[pos] = r << 8;
            }
        }
    }
}

// ---------------- K4: CE over worklist + output + state reset ----------------
__global__ void __launch_bounds__(256)
k_ce(const float* __restrict__ conf_data, float* __restrict__ out) {
    const float NINF = __int_as_float(0xff800000);
    const int lane = threadIdx.x & 31;
    const int wid  = (blockIdx.x * blockDim.x + threadIdx.x) >> 5;
    const int nw   = (gridDim.x * blockDim.x) >> 5;
    int cnt = g_work_cnt;
    float lce = 0.f;

    // early blocks also reset histograms + gt_best for the NEXT replay
    // (hist0/hist1/gt_best are no longer read this replay)
    {
        int t = blockIdx.x * 256 + threadIdx.x;
        if (t < 2048) { g_hist0[t] = 0; g_hist1[t] = 0; }
        if (t >= 2048 && t < 2048 + B_ * N_)
            g_gt_best[t - 2048] = 0x00000000FFFFFFFFull;
    }

    for (int i = wid; i < cnt; i += nw) {
        int item = g_work[i];
        int r  = item >> 8;
        int ct = item & 255;
        const float* row = conf_data + (size_t)r * C_;
        float x0 = row[lane];
        float x1 = row[lane + 32];
        float x2 = (lane < 17) ? row[lane + 64] : NINF;
        float m = fmaxf(x0, fmaxf(x1, x2));
        #pragma unroll
        for (int o = 16; o; o >>= 1)
            m = fmaxf(m, __shfl_xor_sync(0xffffffffu, m, o));
        float s = expf(x0 - m) + expf(x1 - m) + ((lane < 17) ? expf(x2 - m) : 0.f);
        #pragma unroll
        for (int o = 16; o; o >>= 1) s += __shfl_xor_sync(0xffffffffu, s, o);
        float tv = NINF;
        if (lane == ct)                   tv = x0;
        if (lane + 32 == ct)              tv = x1;
        if (lane < 17 && lane + 64 == ct) tv = x2;
        #pragma unroll
        for (int o = 16; o; o >>= 1)
            tv = fmaxf(tv, __shfl_xor_sync(0xffffffffu, tv, o));
        if (lane == 0) lce += (m + logf(s)) - tv;
    }

    #pragma unroll
    for (int o = 16; o; o >>= 1) lce += __shfl_xor_sync(0xffffffffu, lce, o);
    __shared__ float sf[8];
    int w = threadIdx.x >> 5;
    if (lane == 0) sf[w] = lce;
    __syncthreads();
    if (threadIdx.x == 0) {
        float a = 0.f;
        #pragma unroll
        for (int i = 0; i < 8; i++) a += sf[i];
        if (a != 0.f) atomicAdd(&g_ce_sum, a);
        __threadfence();
        int done = atomicAdd(&g_done_ce, 1);
        if (done == (int)gridDim.x - 1) {
            int np = g_num_pos; if (np < 1) np = 1;
            int kp = cnt;       if (kp < 1) kp = 1;
            out[0] = g_sl1    / (float)np;
            out[1] = g_ce_sum / (float)kp;
            // ---- reset remaining state for next replay ----
            g_sl1 = 0.f; g_ce_sum = 0.f;
            g_work_cnt = 0; g_cand_cnt = 0;
            g_num_pos = 0; g_K = 0;
            g_done_match = 0; g_done_conf = 0; g_done_s1 = 0;
            g_done_ce = 0;
            __threadfence();
        }
    }
}

// ---------------- host -------------------------------------------------------
extern "C" void kernel_launch(void* const* d_in, const int* in_sizes, int n_in,
                              void* d_out, int out_size) {
    const float* loc = nullptr;
    const float* conf = nullptr;
    const float* priors = nullptr;
    const float* gtb = nullptr;
    const int*   gtl = nullptr;
    for (int i = 0; i < n_in; i++) {
        long long s = in_sizes[i];
        if      (s == (long long)B_ * P_ * C_) conf   = (const float*)d_in[i];
        else if (s == (long long)B_ * P_ * 4)  loc    = (const float*)d_in[i];
        else if (s == (long long)P_ * 4)       priors = (const float*)d_in[i];
        else if (s == (long long)B_ * N_ * 4)  gtb    = (const float*)d_in[i];
        else if (s == (long long)B_ * N_)      gtl    = (const int*)d_in[i];
    }
    float* out = (float*)d_out;

    k_match<<<dim3((P_ + 255) / 256, B_), 256>>>(priors, gtb);
    k_conf<<<1776, 256>>>(conf, loc, priors, gtb, gtl);
    k_scan1<<<904, 256>>>();
    k_ce<<<464, 256>>>(conf, out);
}

// round 12
// speedup vs baseline: 2.1822x; 2.1822x over previous
#include <cuda_runtime.h>

#define B_ 8
#define P_ 57744
#define C_ 81
#define N_ 20
#define ROWS_ (B_ * P_)
#define POS_TH 0.5f
#define NEG_TH 0.4f
#define CAND_CAP 131072
#define CAND2_CAP 16384
#define SM_CAND 2048

// ---------------- scratch (static __device__, zero-init at load) -------------
// Self-cleaning pipeline: k_ce resets everything for the next replay.
__device__ unsigned char      g_mt[ROWS_];      // (gt_idx<<2)|band; band3=forced
__device__ unsigned long long g_gt_best[B_ * N_];
__device__ unsigned long long g_keys[ROWS_];
__device__ signed char        g_conf[ROWS_];
__device__ int                g_hist0[2048];
__device__ int                g_hist1[2048];
__device__ unsigned long long g_cand[CAND_CAP];
__device__ unsigned long long g_cand2[CAND2_CAP];
__device__ int                g_cand_cnt;
__device__ int                g_cand2_cnt;
__device__ int                g_work[ROWS_];    // (r<<8) | target
__device__ int                g_work_cnt;
__device__ int                g_num_pos;
__device__ int                g_K;
__device__ int                g_d1;
__device__ long long          g_Krem1;
__device__ int                g_d2;
__device__ long long          g_Krem2;
__device__ float              g_sl1;
__device__ float              g_ce_sum;
__device__ int                g_done_match;
__device__ int                g_done_conf;
__device__ int                g_done_s1;
__device__ int                g_done_s2;
__device__ int                g_done_ce;
__device__ int                g_seeded;         // 0 on first run: seed gt_best

__device__ __forceinline__ float smooth_l1(float d) {
    float ad = fabsf(d);
    return ad < 1.f ? 0.5f * d * d : ad - 0.5f;
}
__device__ __forceinline__ unsigned ord_bits(float x) {
    unsigned b = __float_as_uint(x);
    unsigned m = (unsigned)((int)b >> 31) | 0x80000000u;
    return b ^ m;   // monotonic float -> uint
}

// warp-aggregated append (call from ALL lanes, uniform control flow)
__device__ __forceinline__ int warp_append(int* ctr, bool pred) {
    unsigned bal = __ballot_sync(0xffffffffu, pred);
    int lane = threadIdx.x & 31;
    int base = 0;
    int leader = __ffs(bal) - 1;
    if (bal && lane == leader) base = atomicAdd(ctr, __popc(bal));
    base = __shfl_sync(0xffffffffu, base, leader < 0 ? 0 : leader);
    return base + __popc(bal & ((1u << lane) - 1u));
}

// suffix-scan pick over 2048 buckets, 256 threads.
__device__ void pick_digit(const int* hist, long long Krem_in,
                           int& d_out, long long& Krem_out) {
    __shared__ long long suf[256];
    __shared__ int s_d;
    __shared__ long long s_k;
    int t = threadIdx.x;
    int h[8];
    long long s = 0;
    #pragma unroll
    for (int i = 0; i < 8; i++) { h[i] = hist[t * 8 + i]; s += h[i]; }
    suf[t] = s;
    __syncthreads();
    #pragma unroll
    for (int off = 1; off < 256; off <<= 1) {
        long long v = (t + off < 256) ? suf[t + off] : 0;
        __syncthreads();
        suf[t] += v;
        __syncthreads();
    }
    long long above = (t + 1 < 256) ? suf[t + 1] : 0;
    if (suf[t] >= Krem_in && above < Krem_in) {
        long long ab = above;
        int d = t * 8;
        #pragma unroll
        for (int i = 7; i >= 0; i--) {
            if (ab + h[i] >= Krem_in) { d = t * 8 + i; break; }
            ab += h[i];
        }
        s_d = d; s_k = Krem_in - ab;
    }
    __syncthreads();
    d_out = s_d;
    Krem_out = s_k;
}

// ---------------- K1: matching + (last block) force-patch --------------------
__global__ void k_match(const float* __restrict__ priors,
                        const float* __restrict__ gt_boxes) {
    int b = blockIdx.y;
    int p = blockIdx.x * 256 + threadIdx.x;

    __shared__ float4 s_gt[N_];
    __shared__ float  s_area[N_];
    __shared__ unsigned long long s_best[N_];
    // first-ever run: g_gt_best is zero-init; seed fallback keys once
    if (blockIdx.x == 0 && blockIdx.y == 0 && threadIdx.x == 0) {
        if (atomicExch(&g_seeded, 1) == 0) {
            for (int i = 0; i < B_ * N_; i++)
                atomicMax(&g_gt_best[i], 0x00000000FFFFFFFFull);
        }
    }
    if (threadIdx.x < N_) {
        float4 g = reinterpret_cast<const float4*>(gt_boxes)[b * N_ + threadIdx.x];
        s_gt[threadIdx.x] = g;
        s_area[threadIdx.x] = (g.z - g.x) * (g.w - g.y);
        s_best[threadIdx.x] = 0x00000000FFFFFFFFull;  // fallback prior 0
    }
    __syncthreads();

    if (p < P_) {
        float4 pr = reinterpret_cast<const float4*>(priors)[p];
        float px1 = pr.x - pr.z * 0.5f, py1 = pr.y - pr.w * 0.5f;
        float px2 = pr.x + pr.z * 0.5f, py2 = pr.y + pr.w * 0.5f;
        float parea = (px2 - px1) * (py2 - py1);

        float best = 0.f; int bestn = 0;
        #pragma unroll
        for (int n = 0; n < N_; n++) {
            float4 g = s_gt[n];
            float ix1 = fmaxf(px1, g.x), iy1 = fmaxf(py1, g.y);
            float ix2 = fminf(px2, g.z), iy2 = fminf(py2, g.w);
            float iw = fmaxf(ix2 - ix1, 0.f), ih = fmaxf(iy2 - iy1, 0.f);
            float inter = iw * ih;
            float iou = inter / (s_area[n] + parea - inter);
            if (iou > best) { best = iou; bestn = n; }
            if (inter > 0.f) {
                unsigned long long key =
                    (((unsigned long long)__float_as_uint(iou)) << 32) |
                    (unsigned)(~(unsigned)p);
                atomicMax(&s_best[n], key);
            }
        }
        int band = (best < NEG_TH) ? 0 : ((best < POS_TH) ? 1 : 2);
        g_mt[b * P_ + p] = (unsigned char)((bestn << 2) | band);
    }
    __syncthreads();
    if (threadIdx.x < N_)
        atomicMax(&g_gt_best[b * N_ + threadIdx.x], s_best[threadIdx.x]);

    // last block patches forced matches into g_mt (band 3, last-GT-wins)
    __shared__ int s_last;
    __threadfence();
    __syncthreads();
    if (threadIdx.x == 0)
        s_last = (atomicAdd(&g_done_match, 1) ==
                  (int)(gridDim.x * gridDim.y) - 1);
    __syncthreads();
    if (!s_last) return;
    int w  = threadIdx.x >> 5;    // 8 warps = 8 batches
    int ln = threadIdx.x & 31;
    if (ln < N_) {
        unsigned long long key = g_gt_best[w * N_ + ln];
        unsigned p2 = ~(unsigned)(key & 0xFFFFFFFFull);
        unsigned msk = __match_any_sync(0xFFFFFu, p2);
        int winner = 31 - __clz((int)msk);   // highest n among dup priors
        if (ln == winner)
            g_mt[w * P_ + p2] = (unsigned char)((ln << 2) | 3);
    }
}

// ---------------- K2: conf scan + loc loss + hist0 + pick d1 -----------------
__global__ void __launch_bounds__(256, 5)
k_conf(const float* __restrict__ conf_data,
       const float* __restrict__ loc_data,
       const float* __restrict__ priors,
       const float* __restrict__ gt_boxes,
       const int* __restrict__ gt_labels) {
    const float NINF = __int_as_float(0xff800000);
    __shared__ int s_hist[2048];
    __shared__ int s_labels[B_ * N_];
    for (int i = threadIdx.x; i < 2048; i += 256) s_hist[i] = 0;
    if (threadIdx.x < B_ * N_) s_labels[threadIdx.x] = gt_labels[threadIdx.x];
    __syncthreads();

    const int lane = threadIdx.x & 31;
    const int wid  = (blockIdx.x * blockDim.x + threadIdx.x) >> 5;
    const int nw   = (gridDim.x * blockDim.x) >> 5;

    float lsl = 0.f;
    const int NCH = ROWS_ / 8;
    const unsigned long long* mtp =
        reinterpret_cast<const unsigned long long*>(g_mt);

    for (int ch = wid; ch < NCH; ch += nw) {
        int r0 = ch * 8;
        unsigned long long mt8 = __ldg(mtp + ch);
        const float* base = conf_data + (size_t)r0 * C_;
        float fr[8];
        #pragma unroll
        for (int j = 0; j < 8; j++) {
            const float* row = base + j * C_;
            float a  = __ldcs(row + lane);
            float b2 = __ldcs(row + lane + 32);
            float c2 = (lane < 17) ? __ldcs(row + lane + 64) : NINF;
            fr[j] = fmaxf(fmaxf(lane ? a : NINF, b2), c2);
        }
        unsigned mr[8];
        #pragma unroll
        for (int j = 0; j < 8; j++)
            mr[j] = __reduce_max_sync(0xffffffffu, ord_bits(fr[j]));

        if (lane < 8) {
            unsigned uu = (lane & 4)
                ? ((lane & 2) ? ((lane & 1) ? mr[7] : mr[6])
                              : ((lane & 1) ? mr[5] : mr[4]))
                : ((lane & 2) ? ((lane & 1) ? mr[3] : mr[2])
                              : ((lane & 1) ? mr[1] : mr[0]));
            int r = r0 + lane;
            int b = r / P_;
            int p = r - b * P_;
            unsigned mt = (unsigned)((mt8 >> (lane * 8)) & 0xFF);
            int band = mt & 3;
            int n = mt >> 2;
            int c = (band == 0) ? 0 : ((band == 1) ? -1 : s_labels[b * N_ + n]);
            g_conf[r] = (signed char)c;
            unsigned u = (c == 0) ? uu : 0u;
            unsigned long long key =
                (((unsigned long long)u) << 32) | (unsigned)(~(unsigned)r);
            g_keys[r] = key;
            atomicAdd(&s_hist[(int)(key >> 53)], 1);
            if (c > 0) {
                float4 pr = reinterpret_cast<const float4*>(priors)[p];
                float4 g  = reinterpret_cast<const float4*>(gt_boxes)[b * N_ + n];
                float4 ld = reinterpret_cast<const float4*>(loc_data)[r];
                float tx = ((g.x + g.z) * 0.5f - pr.x) / (0.1f * pr.z);
                float ty = ((g.y + g.w) * 0.5f - pr.y) / (0.1f * pr.w);
                float tw = logf((g.z - g.x) / pr.z) * 5.0f;
                float th = logf((g.w - g.y) / pr.w) * 5.0f;
                lsl += smooth_l1(ld.x - tx) + smooth_l1(ld.y - ty)
                     + smooth_l1(ld.z - tw) + smooth_l1(ld.w - th);
                int pos = atomicAdd(&g_work_cnt, 1);   // ~700 total: cheap
                g_work[pos] = (r << 8) | c;
            }
        }
    }

    #pragma unroll
    for (int o = 16; o; o >>= 1) lsl += __shfl_xor_sync(0xffffffffu, lsl, o);
    __shared__ float sf[8];
    int w = threadIdx.x >> 5;
    if (lane == 0) sf[w] = lsl;
    __syncthreads();
    if (threadIdx.x == 0) {
        float a = 0.f;
        #pragma unroll
        for (int i = 0; i < 8; i++) a += sf[i];
        if (a != 0.f) atomicAdd(&g_sl1, a);
    }
    __syncthreads();
    for (int i = threadIdx.x; i < 2048; i += 256) {
        int v = s_hist[i];
        if (v) atomicAdd(&g_hist0[i], v);
    }

    // last block: num_pos from worklist (all entries are positives), pick d1
    __shared__ int s_last;
    __threadfence();
    if (threadIdx.x == 0)
        s_last = (atomicAdd(&g_done_conf, 1) == (int)gridDim.x - 1);
    __syncthreads();
    if (!s_last) return;
    int np = g_work_cnt;
    long long K = 3LL * np;
    if (K > ROWS_) K = ROWS_;
    if (threadIdx.x == 0) { g_num_pos = np; g_K = (int)K; }
    if (K == 0) return;
    int d1; long long kr;
    pick_digit(g_hist0, K, d1, kr);
    if (threadIdx.x == 0) { g_d1 = d1; g_Krem1 = kr; }
}

// ---------------- K3: one-element-per-thread key scan + hist1 + pick d2 ------
__global__ void __launch_bounds__(256) k_scan1() {
    if (g_K == 0) return;
    const unsigned long long D1 = (unsigned long long)g_d1;
    __shared__ int sh[2048];
    for (int i = threadIdx.x; i < 2048; i += 256) sh[i] = 0;
    __syncthreads();

    int i = blockIdx.x * 256 + threadIdx.x;
    bool in = (i < ROWS_ / 2);
    ulonglong2 kk = in ? reinterpret_cast<const ulonglong2*>(g_keys)[i]
                       : make_ulonglong2(0, 0);
    #pragma unroll
    for (int j = 0; j < 2; j++) {
        unsigned long long key = j ? kk.y : kk.x;
        unsigned long long d = key >> 53;
        bool is_cand = in && (d == D1);
        bool is_keep = in && (d > D1);
        if (is_cand) atomicAdd(&sh[(int)((key >> 42) & 2047)], 1);
        int cslot = warp_append(&g_cand_cnt, is_cand);
        if (is_cand && cslot < CAND_CAP) g_cand[cslot] = key;
        int kslot = warp_append(&g_work_cnt, is_keep);
        if (is_keep)
            g_work[kslot] = ((int)(~(unsigned)(key & 0xFFFFFFFFull))) << 8;
    }
    __syncthreads();
    for (int i2 = threadIdx.x; i2 < 2048; i2 += 256) {
        int v = sh[i2];
        if (v) atomicAdd(&g_hist1[i2], v);
    }

    __shared__ int s_last;
    __threadfence();
    if (threadIdx.x == 0)
        s_last = (atomicAdd(&g_done_s1, 1) == (int)gridDim.x - 1);
    __syncthreads();
    if (!s_last) return;
    int d2; long long kr;
    pick_digit(g_hist1, g_Krem1, d2, kr);
    if (threadIdx.x == 0) { g_d2 = d2; g_Krem2 = kr; }
}

// ---------------- K4: cand scan (parallel!) + last-block exact resolve -------
__global__ void __launch_bounds__(256) k_scan2() {
    if (g_K == 0) return;
    const unsigned long long D2 = (unsigned long long)g_d2;
    int cnt = g_cand_cnt;
    if (cnt > CAND_CAP) cnt = CAND_CAP;

    int t = blockIdx.x * 256 + threadIdx.x;
    int stride = gridDim.x * 256;
    int iters = (cnt + stride - 1) / stride;
    for (int it = 0; it < iters; it++) {
        int i = t + it * stride;
        bool in = (i < cnt);
        unsigned long long key = in ? g_cand[i] : 0ull;
        unsigned long long mid = (key >> 42) & 2047;
        bool is_tie = in && (mid == D2);
        bool pre    = in && (mid > D2);
        int r = pre ? (int)(~(unsigned)(key & 0xFFFFFFFFull)) : 0;
        bool is_keep = pre && (g_conf[r] == 0);
        int cslot = warp_append(&g_cand2_cnt, is_tie);
        if (is_tie && cslot < CAND2_CAP) g_cand2[cslot] = key;
        int kslot = warp_append(&g_work_cnt, is_keep);
        if (is_keep) g_work[kslot] = r << 8;
    }

    // last block: exact resolve of remaining 42 bits (warp 0)
    __shared__ int s_last;
    __shared__ unsigned long long s_cand[SM_CAND];
    __threadfence();
    if (threadIdx.x == 0)
        s_last = (atomicAdd(&g_done_s2, 1) == (int)gridDim.x - 1);
    __syncthreads();
    if (!s_last) return;

    int c2 = g_cand2_cnt;
    if (c2 > CAND2_CAP) c2 = CAND2_CAP;
    bool in_sm = (c2 <= SM_CAND);
    if (in_sm)
        for (int i = threadIdx.x; i < c2; i += 256) s_cand[i] = g_cand2[i];
    __syncthreads();
    if (threadIdx.x >= 32) return;

    int lane = threadIdx.x;
    unsigned long long F =
        (((unsigned long long)g_d1) << 11) | (unsigned long long)g_d2;
    long long Kr = g_Krem2;
    for (int b = 41; b >= 0; b--) {
        int local = 0;
        for (int i = lane; i < c2; i += 32) {
            unsigned long long k2 = in_sm ? s_cand[i] : g_cand2[i];
            if ((k2 >> (b + 1)) == F && ((k2 >> b) & 1ull)) local++;
        }
        int c1 = __reduce_add_sync(0xffffffffu, local);
        if (c1 >= Kr) F = (F << 1) | 1ull;
        else { Kr -= c1; F <<= 1; }
    }
    for (int i = lane; i < c2; i += 32) {
        unsigned long long k2 = in_sm ? s_cand[i] : g_cand2[i];
        if (k2 >= F) {
            int r = (int)(~(unsigned)(k2 & 0xFFFFFFFFull));
            if (g_conf[r] == 0) {
                int pos = atomicAdd(&g_work_cnt, 1);
                g_work[pos] = r << 8;
            }
        }
    }
}

// ---------------- K5: CE over worklist + output + state reset ----------------
__global__ void __launch_bounds__(256)
k_ce(const float* __restrict__ conf_data, float* __restrict__ out) {
    const float NINF = __int_as_float(0xff800000);
    const int lane = threadIdx.x & 31;
    const int wid  = (blockIdx.x * blockDim.x + threadIdx.x) >> 5;
    const int nw   = (gridDim.x * blockDim.x) >> 5;
    int cnt = g_work_cnt;
    float lce = 0.f;

    // early blocks reset histograms + gt_best for the NEXT replay
    {
        int t = blockIdx.x * 256 + threadIdx.x;
        if (t < 2048) { g_hist0[t] = 0; g_hist1[t] = 0; }
        if (t >= 2048 && t < 2048 + B_ * N_)
            g_gt_best[t - 2048] = 0x00000000FFFFFFFFull;
    }

    for (int i = wid; i < cnt; i += nw) {
        int item = g_work[i];
        int r  = item >> 8;
        int ct = item & 255;
        const float* row = conf_data + (size_t)r * C_;
        float x0 = row[lane];
        float x1 = row[lane + 32];
        float x2 = (lane < 17) ? row[lane + 64] : NINF;
        float m = fmaxf(x0, fmaxf(x1, x2));
        #pragma unroll
        for (int o = 16; o; o >>= 1)
            m = fmaxf(m, __shfl_xor_sync(0xffffffffu, m, o));
        float s = expf(x0 - m) + expf(x1 - m) + ((lane < 17) ? expf(x2 - m) : 0.f);
        #pragma unroll
        for (int o = 16; o; o >>= 1) s += __shfl_xor_sync(0xffffffffu, s, o);
        float tv = NINF;
        if (lane == ct)                   tv = x0;
        if (lane + 32 == ct)              tv = x1;
        if (lane < 17 && lane + 64 == ct) tv = x2;
        #pragma unroll
        for (int o = 16; o; o >>= 1)
            tv = fmaxf(tv, __shfl_xor_sync(0xffffffffu, tv, o));
        if (lane == 0) lce += (m + logf(s)) - tv;
    }

    #pragma unroll
    for (int o = 16; o; o >>= 1) lce += __shfl_xor_sync(0xffffffffu, lce, o);
    __shared__ float sf[8];
    int w = threadIdx.x >> 5;
    if (lane == 0) sf[w] = lce;
    __syncthreads();
    if (threadIdx.x == 0) {
        float a = 0.f;
        #pragma unroll
        for (int i = 0; i < 8; i++) a += sf[i];
        if (a != 0.f) atomicAdd(&g_ce_sum, a);
        __threadfence();
        int done = atomicAdd(&g_done_ce, 1);
        if (done == (int)gridDim.x - 1) {
            int np = g_num_pos; if (np < 1) np = 1;
            int kp = cnt;       if (kp < 1) kp = 1;
            out[0] = g_sl1    / (float)np;
            out[1] = g_ce_sum / (float)kp;
            // ---- reset remaining state for next replay ----
            g_sl1 = 0.f; g_ce_sum = 0.f;
            g_work_cnt = 0; g_cand_cnt = 0; g_cand2_cnt = 0;
            g_num_pos = 0; g_K = 0;
            g_done_match = 0; g_done_conf = 0; g_done_s1 = 0;
            g_done_s2 = 0; g_done_ce = 0;
            __threadfence();
        }
    }
}

// ---------------- host -------------------------------------------------------
extern "C" void kernel_launch(void* const* d_in, const int* in_sizes, int n_in,
                              void* d_out, int out_size) {
    const float* loc = nullptr;
    const float* conf = nullptr;
    const float* priors = nullptr;
    const float* gtb = nullptr;
    const int*   gtl = nullptr;
    for (int i = 0; i < n_in; i++) {
        long long s = in_sizes[i];
        if      (s == (long long)B_ * P_ * C_) conf   = (const float*)d_in[i];
        else if (s == (long long)B_ * P_ * 4)  loc    = (const float*)d_in[i];
        else if (s == (long long)P_ * 4)       priors = (const float*)d_in[i];
        else if (s == (long long)B_ * N_ * 4)  gtb    = (const float*)d_in[i];
        else if (s == (long long)B_ * N_)      gtl    = (const int*)d_in[i];
    }
    float* out = (float*)d_out;

    k_match<<<dim3((P_ + 255) / 256, B_), 256>>>(priors, gtb);
    k_conf<<<1776, 256>>>(conf, loc, priors, gtb, gtl);
    k_scan1<<<904, 256>>>();
    k_scan2<<<592, 256>>>();
    k_ce<<<464, 256>>>(conf, out);
}

// round 13
// speedup vs baseline: 2.2562x; 1.0339x over previous
#include <cuda_runtime.h>

#define B_ 8
#define P_ 57744
#define C_ 81
#define N_ 20
#define ROWS_ (B_ * P_)
#define POS_TH 0.5f
#define NEG_TH 0.4f
#define CAND_CAP 131072
#define CAND2_CAP 16384
#define SM_CAND 2048

// ---------------- scratch (static __device__, zero-init at load) -------------
// Self-cleaning pipeline: k_ce resets everything for the next replay.
__device__ unsigned char      g_mt[ROWS_];      // (gt_idx<<2)|band; band3=forced
__device__ unsigned long long g_gt_best[B_ * N_];
__device__ unsigned          g_umax[ROWS_];     // per-row fg-score ord bits
__device__ unsigned long long g_keys[ROWS_];
__device__ signed char        g_conf[ROWS_];
__device__ int                g_hist0[2048];
__device__ int                g_hist1[2048];
__device__ unsigned long long g_cand[CAND_CAP];
__device__ unsigned long long g_cand2[CAND2_CAP];
__device__ int                g_cand_cnt;
__device__ int                g_cand2_cnt;
__device__ int                g_work[ROWS_];    // (r<<8) | target
__device__ int                g_work_cnt;
__device__ int                g_num_pos;
__device__ int                g_K;
__device__ int                g_d1;
__device__ long long          g_Krem1;
__device__ int                g_d2;
__device__ long long          g_Krem2;
__device__ float              g_sl1;
__device__ float              g_ce_sum;
__device__ int                g_done_match;
__device__ int                g_done_tail;
__device__ int                g_done_s1;
__device__ int                g_done_s2;
__device__ int                g_done_ce;
__device__ int                g_seeded;         // 0 on first run: seed gt_best

__device__ __forceinline__ float smooth_l1(float d) {
    float ad = fabsf(d);
    return ad < 1.f ? 0.5f * d * d : ad - 0.5f;
}
__device__ __forceinline__ unsigned ord_bits(float x) {
    unsigned b = __float_as_uint(x);
    unsigned m = (unsigned)((int)b >> 31) | 0x80000000u;
    return b ^ m;   // monotonic float -> uint
}

// warp-aggregated append (call from ALL lanes, uniform control flow)
__device__ __forceinline__ int warp_append(int* ctr, bool pred) {
    unsigned bal = __ballot_sync(0xffffffffu, pred);
    int lane = threadIdx.x & 31;
    int base = 0;
    int leader = __ffs(bal) - 1;
    if (bal && lane == leader) base = atomicAdd(ctr, __popc(bal));
    base = __shfl_sync(0xffffffffu, base, leader < 0 ? 0 : leader);
    return base + __popc(bal & ((1u << lane) - 1u));
}

// suffix-scan pick over 2048 buckets, 256 threads.
__device__ void pick_digit(const int* hist, long long Krem_in,
                           int& d_out, long long& Krem_out) {
    __shared__ long long suf[256];
    __shared__ int s_d;
    __shared__ long long s_k;
    int t = threadIdx.x;
    int h[8];
    long long s = 0;
    #pragma unroll
    for (int i = 0; i < 8; i++) { h[i] = hist[t * 8 + i]; s += h[i]; }
    suf[t] = s;
    __syncthreads();
    #pragma unroll
    for (int off = 1; off < 256; off <<= 1) {
        long long v = (t + off < 256) ? suf[t + off] : 0;
        __syncthreads();
        suf[t] += v;
        __syncthreads();
    }
    long long above = (t + 1 < 256) ? suf[t + 1] : 0;
    if (suf[t] >= Krem_in && above < Krem_in) {
        long long ab = above;
        int d = t * 8;
        #pragma unroll
        for (int i = 7; i >= 0; i--) {
            if (ab + h[i] >= Krem_in) { d = t * 8 + i; break; }
            ab += h[i];
        }
        s_d = d; s_k = Krem_in - ab;
    }
    __syncthreads();
    d_out = s_d;
    Krem_out = s_k;
}

// ---------------- K-A: pure conf max-scan (150 MB, NO dependencies) ----------
__global__ void __launch_bounds__(256, 8)
k_max(const float* __restrict__ conf_data) {
    const float NINF = __int_as_float(0xff800000);
    const int lane = threadIdx.x & 31;
    const int wid  = (blockIdx.x * blockDim.x + threadIdx.x) >> 5;
    const int nw   = (gridDim.x * blockDim.x) >> 5;
    const int NCH = ROWS_ / 8;

    for (int ch = wid; ch < NCH; ch += nw) {
        const float* base = conf_data + (size_t)(ch * 8) * C_;
        float fr[8];
        #pragma unroll
        for (int j = 0; j < 8; j++) {
            const float* row = base + j * C_;
            float a  = __ldcs(row + lane);
            float b2 = __ldcs(row + lane + 32);
            float c2 = (lane < 17) ? __ldcs(row + lane + 64) : NINF;
            fr[j] = fmaxf(fmaxf(lane ? a : NINF, b2), c2);
        }
        unsigned mr[8];
        #pragma unroll
        for (int j = 0; j < 8; j++)
            mr[j] = __reduce_max_sync(0xffffffffu, ord_bits(fr[j]));
        if (lane < 8) {
            unsigned uu = (lane & 4)
                ? ((lane & 2) ? ((lane & 1) ? mr[7] : mr[6])
                              : ((lane & 1) ? mr[5] : mr[4]))
                : ((lane & 2) ? ((lane & 1) ? mr[3] : mr[2])
                              : ((lane & 1) ? mr[1] : mr[0]));
            g_umax[ch * 8 + lane] = uu;
        }
    }
}

// ---------------- K-B: matching + (last block) force-patch (side stream) -----
__global__ void k_match(const float* __restrict__ priors,
                        const float* __restrict__ gt_boxes) {
    int b = blockIdx.y;
    int p = blockIdx.x * 256 + threadIdx.x;

    __shared__ float4 s_gt[N_];
    __shared__ float  s_area[N_];
    __shared__ unsigned long long s_best[N_];
    if (blockIdx.x == 0 && blockIdx.y == 0 && threadIdx.x == 0) {
        if (atomicExch(&g_seeded, 1) == 0) {
            for (int i = 0; i < B_ * N_; i++)
                atomicMax(&g_gt_best[i], 0x00000000FFFFFFFFull);
        }
    }
    if (threadIdx.x < N_) {
        float4 g = reinterpret_cast<const float4*>(gt_boxes)[b * N_ + threadIdx.x];
        s_gt[threadIdx.x] = g;
        s_area[threadIdx.x] = (g.z - g.x) * (g.w - g.y);
        s_best[threadIdx.x] = 0x00000000FFFFFFFFull;  // fallback prior 0
    }
    __syncthreads();

    if (p < P_) {
        float4 pr = reinterpret_cast<const float4*>(priors)[p];
        float px1 = pr.x - pr.z * 0.5f, py1 = pr.y - pr.w * 0.5f;
        float px2 = pr.x + pr.z * 0.5f, py2 = pr.y + pr.w * 0.5f;
        float parea = (px2 - px1) * (py2 - py1);

        float best = 0.f; int bestn = 0;
        #pragma unroll
        for (int n = 0; n < N_; n++) {
            float4 g = s_gt[n];
            float ix1 = fmaxf(px1, g.x), iy1 = fmaxf(py1, g.y);
            float ix2 = fminf(px2, g.z), iy2 = fminf(py2, g.w);
            float iw = fmaxf(ix2 - ix1, 0.f), ih = fmaxf(iy2 - iy1, 0.f);
            float inter = iw * ih;
            float iou = inter / (s_area[n] + parea - inter);
            if (iou > best) { best = iou; bestn = n; }
            if (inter > 0.f) {
                unsigned long long key =
                    (((unsigned long long)__float_as_uint(iou)) << 32) |
                    (unsigned)(~(unsigned)p);
                atomicMax(&s_best[n], key);
            }
        }
        int band = (best < NEG_TH) ? 0 : ((best < POS_TH) ? 1 : 2);
        g_mt[b * P_ + p] = (unsigned char)((bestn << 2) | band);
    }
    __syncthreads();
    if (threadIdx.x < N_)
        atomicMax(&g_gt_best[b * N_ + threadIdx.x], s_best[threadIdx.x]);

    // last block patches forced matches into g_mt (band 3, last-GT-wins)
    __shared__ int s_last;
    __threadfence();
    __syncthreads();
    if (threadIdx.x == 0)
        s_last = (atomicAdd(&g_done_match, 1) ==
                  (int)(gridDim.x * gridDim.y) - 1);
    __syncthreads();
    if (!s_last) return;
    int w  = threadIdx.x >> 5;    // 8 warps = 8 batches
    int ln = threadIdx.x & 31;
    if (ln < N_) {
        unsigned long long key = g_gt_best[w * N_ + ln];
        unsigned p2 = ~(unsigned)(key & 0xFFFFFFFFull);
        unsigned msk = __match_any_sync(0xFFFFFu, p2);
        int winner = 31 - __clz((int)msk);   // highest n among dup priors
        if (ln == winner)
            g_mt[w * P_ + p2] = (unsigned char)((ln << 2) | 3);
    }
}

// ---------------- K-C: tail: conf/keys/hist0/loc-loss + pick d1 --------------
__global__ void __launch_bounds__(256)
k_tail(const float* __restrict__ loc_data,
       const float* __restrict__ priors,
       const float* __restrict__ gt_boxes,
       const int* __restrict__ gt_labels) {
    __shared__ int s_hist[2048];
    __shared__ int s_labels[B_ * N_];
    for (int i = threadIdx.x; i < 2048; i += 256) s_hist[i] = 0;
    if (threadIdx.x < B_ * N_) s_labels[threadIdx.x] = gt_labels[threadIdx.x];
    __syncthreads();

    const int lane = threadIdx.x & 31;
    float lsl = 0.f;
    int t = blockIdx.x * 256 + threadIdx.x;
    int stride = gridDim.x * 256;

    for (int r = t; r < ROWS_; r += stride) {
        unsigned uu = g_umax[r];
        unsigned mt = g_mt[r];
        int b = r / P_;
        int band = mt & 3;
        int n = mt >> 2;
        int c = (band == 0) ? 0 : ((band == 1) ? -1 : s_labels[b * N_ + n]);
        g_conf[r] = (signed char)c;
        unsigned u = (c == 0) ? uu : 0u;
        unsigned long long key =
            (((unsigned long long)u) << 32) | (unsigned)(~(unsigned)r);
        g_keys[r] = key;
        atomicAdd(&s_hist[(int)(key >> 53)], 1);
        if (c > 0) {
            int p = r - b * P_;
            float4 pr = reinterpret_cast<const float4*>(priors)[p];
            float4 g  = reinterpret_cast<const float4*>(gt_boxes)[b * N_ + n];
            float4 ld = reinterpret_cast<const float4*>(loc_data)[r];
            float tx = ((g.x + g.z) * 0.5f - pr.x) / (0.1f * pr.z);
            float ty = ((g.y + g.w) * 0.5f - pr.y) / (0.1f * pr.w);
            float tw = logf((g.z - g.x) / pr.z) * 5.0f;
            float th = logf((g.w - g.y) / pr.w) * 5.0f;
            lsl += smooth_l1(ld.x - tx) + smooth_l1(ld.y - ty)
                 + smooth_l1(ld.z - tw) + smooth_l1(ld.w - th);
            int pos = atomicAdd(&g_work_cnt, 1);   // ~700 total: cheap
            g_work[pos] = (r << 8) | c;
        }
    }

    #pragma unroll
    for (int o = 16; o; o >>= 1) lsl += __shfl_xor_sync(0xffffffffu, lsl, o);
    __shared__ float sf[8];
    int w = threadIdx.x >> 5;
    if (lane == 0) sf[w] = lsl;
    __syncthreads();
    if (threadIdx.x == 0) {
        float a = 0.f;
        #pragma unroll
        for (int i = 0; i < 8; i++) a += sf[i];
        if (a != 0.f) atomicAdd(&g_sl1, a);
    }
    __syncthreads();
    for (int i = threadIdx.x; i < 2048; i += 256) {
        int v = s_hist[i];
        if (v) atomicAdd(&g_hist0[i], v);
    }

    // last block: num_pos from worklist (all entries are positives), pick d1
    __shared__ int s_last;
    __threadfence();
    if (threadIdx.x == 0)
        s_last = (atomicAdd(&g_done_tail, 1) == (int)gridDim.x - 1);
    __syncthreads();
    if (!s_last) return;
    int np = g_work_cnt;
    long long K = 3LL * np;
    if (K > ROWS_) K = ROWS_;
    if (threadIdx.x == 0) { g_num_pos = np; g_K = (int)K; }
    if (K == 0) return;
    int d1; long long kr;
    pick_digit(g_hist0, K, d1, kr);
    if (threadIdx.x == 0) { g_d1 = d1; g_Krem1 = kr; }
}

// ---------------- K3: key scan + hist1 + pick d2 -----------------------------
__global__ void __launch_bounds__(256) k_scan1() {
    if (g_K == 0) return;
    const unsigned long long D1 = (unsigned long long)g_d1;
    __shared__ int sh[2048];
    for (int i = threadIdx.x; i < 2048; i += 256) sh[i] = 0;
    __syncthreads();

    int i = blockIdx.x * 256 + threadIdx.x;
    bool in = (i < ROWS_ / 2);
    ulonglong2 kk = in ? reinterpret_cast<const ulonglong2*>(g_keys)[i]
                       : make_ulonglong2(0, 0);
    #pragma unroll
    for (int j = 0; j < 2; j++) {
        unsigned long long key = j ? kk.y : kk.x;
        unsigned long long d = key >> 53;
        bool is_cand = in && (d == D1);
        bool is_keep = in && (d > D1);
        if (is_cand) atomicAdd(&sh[(int)((key >> 42) & 2047)], 1);
        int cslot = warp_append(&g_cand_cnt, is_cand);
        if (is_cand && cslot < CAND_CAP) g_cand[cslot] = key;
        int kslot = warp_append(&g_work_cnt, is_keep);
        if (is_keep)
            g_work[kslot] = ((int)(~(unsigned)(key & 0xFFFFFFFFull))) << 8;
    }
    __syncthreads();
    for (int i2 = threadIdx.x; i2 < 2048; i2 += 256) {
        int v = sh[i2];
        if (v) atomicAdd(&g_hist1[i2], v);
    }

    __shared__ int s_last;
    __threadfence();
    if (threadIdx.x == 0)
        s_last = (atomicAdd(&g_done_s1, 1) == (int)gridDim.x - 1);
    __syncthreads();
    if (!s_last) return;
    int d2; long long kr;
    pick_digit(g_hist1, g_Krem1, d2, kr);
    if (threadIdx.x == 0) { g_d2 = d2; g_Krem2 = kr; }
}

// ---------------- K4: cand scan + last-block exact resolve -------------------
__global__ void __launch_bounds__(256) k_scan2() {
    if (g_K == 0) return;
    const unsigned long long D2 = (unsigned long long)g_d2;
    int cnt = g_cand_cnt;
    if (cnt > CAND_CAP) cnt = CAND_CAP;

    int t = blockIdx.x * 256 + threadIdx.x;
    int stride = gridDim.x * 256;
    int iters = (cnt + stride - 1) / stride;
    for (int it = 0; it < iters; it++) {
        int i = t + it * stride;
        bool in = (i < cnt);
        unsigned long long key = in ? g_cand[i] : 0ull;
        unsigned long long mid = (key >> 42) & 2047;
        bool is_tie = in && (mid == D2);
        bool pre    = in && (mid > D2);
        int r = pre ? (int)(~(unsigned)(key & 0xFFFFFFFFull)) : 0;
        bool is_keep = pre && (g_conf[r] == 0);
        int cslot = warp_append(&g_cand2_cnt, is_tie);
        if (is_tie && cslot < CAND2_CAP) g_cand2[cslot] = key;
        int kslot = warp_append(&g_work_cnt, is_keep);
        if (is_keep) g_work[kslot] = r << 8;
    }

    // last block: exact resolve of remaining 42 bits (warp 0)
    __shared__ int s_last;
    __shared__ unsigned long long s_cand[SM_CAND];
    __threadfence();
    if (threadIdx.x == 0)
        s_last = (atomicAdd(&g_done_s2, 1) == (int)gridDim.x - 1);
    __syncthreads();
    if (!s_last) return;

    int c2 = g_cand2_cnt;
    if (c2 > CAND2_CAP) c2 = CAND2_CAP;
    bool in_sm = (c2 <= SM_CAND);
    if (in_sm)
        for (int i = threadIdx.x; i < c2; i += 256) s_cand[i] = g_cand2[i];
    __syncthreads();
    if (threadIdx.x >= 32) return;

    int lane = threadIdx.x;
    unsigned long long F =
        (((unsigned long long)g_d1) << 11) | (unsigned long long)g_d2;
    long long Kr = g_Krem2;
    for (int b = 41; b >= 0; b--) {
        int local = 0;
        for (int i = lane; i < c2; i += 32) {
            unsigned long long k2 = in_sm ? s_cand[i] : g_cand2[i];
            if ((k2 >> (b + 1)) == F && ((k2 >> b) & 1ull)) local++;
        }
        int c1 = __reduce_add_sync(0xffffffffu, local);
        if (c1 >= Kr) F = (F << 1) | 1ull;
        else { Kr -= c1; F <<= 1; }
    }
    for (int i = lane; i < c2; i += 32) {
        unsigned long long k2 = in_sm ? s_cand[i] : g_cand2[i];
        if (k2 >= F) {
            int r = (int)(~(unsigned)(k2 & 0xFFFFFFFFull));
            if (g_conf[r] == 0) {
                int pos = atomicAdd(&g_work_cnt, 1);
                g_work[pos] = r << 8;
            }
        }
    }
}

// ---------------- K5: CE over worklist + output + state reset ----------------
__global__ void __launch_bounds__(256)
k_ce(const float* __restrict__ conf_data, float* __restrict__ out) {
    const float NINF = __int_as_float(0xff800000);
    const int lane = threadIdx.x & 31;
    const int wid  = (blockIdx.x * blockDim.x + threadIdx.x) >> 5;
    const int nw   = (gridDim.x * blockDim.x) >> 5;
    int cnt = g_work_cnt;
    float lce = 0.f;

    // early blocks reset histograms + gt_best for the NEXT replay
    {
        int t = blockIdx.x * 256 + threadIdx.x;
        if (t < 2048) { g_hist0[t] = 0; g_hist1[t] = 0; }
        if (t >= 2048 && t < 2048 + B_ * N_)
            g_gt_best[t - 2048] = 0x00000000FFFFFFFFull;
    }

    for (int i = wid; i < cnt; i += nw) {
        int item = g_work[i];
        int r  = item >> 8;
        int ct = item & 255;
        const float* row = conf_data + (size_t)r * C_;
        float x0 = row[lane];
        float x1 = row[lane + 32];
        float x2 = (lane < 17) ? row[lane + 64] : NINF;
        float m = fmaxf(x0, fmaxf(x1, x2));
        #pragma unroll
        for (int o = 16; o; o >>= 1)
            m = fmaxf(m, __shfl_xor_sync(0xffffffffu, m, o));
        float s = expf(x0 - m) + expf(x1 - m) + ((lane < 17) ? expf(x2 - m) : 0.f);
        #pragma unroll
        for (int o = 16; o; o >>= 1) s += __shfl_xor_sync(0xffffffffu, s, o);
        float tv = NINF;
        if (lane == ct)                   tv = x0;
        if (lane + 32 == ct)              tv = x1;
        if (lane < 17 && lane + 64 == ct) tv = x2;
        #pragma unroll
        for (int o = 16; o; o >>= 1)
            tv = fmaxf(tv, __shfl_xor_sync(0xffffffffu, tv, o));
        if (lane == 0) lce += (m + logf(s)) - tv;
    }

    #pragma unroll
    for (int o = 16; o; o >>= 1) lce += __shfl_xor_sync(0xffffffffu, lce, o);
    __shared__ float sf[8];
    int w = threadIdx.x >> 5;
    if (lane == 0) sf[w] = lce;
    __syncthreads();
    if (threadIdx.x == 0) {
        float a = 0.f;
        #pragma unroll
        for (int i = 0; i < 8; i++) a += sf[i];
        if (a != 0.f) atomicAdd(&g_ce_sum, a);
        __threadfence();
        int done = atomicAdd(&g_done_ce, 1);
        if (done == (int)gridDim.x - 1) {
            int np = g_num_pos; if (np < 1) np = 1;
            int kp = cnt;       if (kp < 1) kp = 1;
            out[0] = g_sl1    / (float)np;
            out[1] = g_ce_sum / (float)kp;
            // ---- reset remaining state for next replay ----
            g_sl1 = 0.f; g_ce_sum = 0.f;
            g_work_cnt = 0; g_cand_cnt = 0; g_cand2_cnt = 0;
            g_num_pos = 0; g_K = 0;
            g_done_match = 0; g_done_tail = 0; g_done_s1 = 0;
            g_done_s2 = 0; g_done_ce = 0;
            __threadfence();
        }
    }
}

// ---------------- host -------------------------------------------------------
extern "C" void kernel_launch(void* const* d_in, const int* in_sizes, int n_in,
                              void* d_out, int out_size) {
    const float* loc = nullptr;
    const float* conf = nullptr;
    const float* priors = nullptr;
    const float* gtb = nullptr;
    const int*   gtl = nullptr;
    for (int i = 0; i < n_in; i++) {
        long long s = in_sizes[i];
        if      (s == (long long)B_ * P_ * C_) conf   = (const float*)d_in[i];
        else if (s == (long long)B_ * P_ * 4)  loc    = (const float*)d_in[i];
        else if (s == (long long)P_ * 4)       priors = (const float*)d_in[i];
        else if (s == (long long)B_ * N_ * 4)  gtb    = (const float*)d_in[i];
        else if (s == (long long)B_ * N_)      gtl    = (const int*)d_in[i];
    }
    float* out = (float*)d_out;

    // capture-safe stream fork: k_match (side) overlaps k_max (main)
    static cudaStream_t s_side = nullptr;
    static cudaEvent_t  e_fork = nullptr, e_join = nullptr;
    if (!s_side) {
        cudaStreamCreateWithFlags(&s_side, cudaStreamNonBlocking);
        cudaEventCreateWithFlags(&e_fork, cudaEventDisableTiming);
        cudaEventCreateWithFlags(&e_join, cudaEventDisableTiming);
    }

    cudaEventRecord(e_fork, 0);
    cudaStreamWaitEvent(s_side, e_fork, 0);
    k_match<<<dim3((P_ + 255) / 256, B_), 256, 0, s_side>>>(priors, gtb);
    cudaEventRecord(e_join, s_side);

    k_max<<<1776, 256>>>(conf);          // concurrent with k_match

    cudaStreamWaitEvent(0, e_join, 0);   // join before tail
    k_tail<<<904, 256>>>(loc, priors, gtb, gtl);
    k_scan1<<<904, 256>>>();
    k_scan2<<<592, 256>>>();
    k_ce<<<464, 256>>>(conf, out);
}

// round 14
// speedup vs baseline: 2.2668x; 1.0047x over previous
#include <cuda_runtime.h>

#define B_ 8
#define P_ 57744
#define C_ 81
#define N_ 20
#define ROWS_ (B_ * P_)
#define POS_TH 0.5f
#define NEG_TH 0.4f
#define CAND_CAP 131072
#define CAND2_CAP 16384
#define SM_CAND 2048

// ---------------- scratch (static __device__, zero-init at load) -------------
// Self-cleaning pipeline: k_ce resets everything for the next replay.
__device__ unsigned char      g_mt[ROWS_];      // (gt_idx<<2)|band; band3=forced
__device__ unsigned long long g_gt_best[B_ * N_];
__device__ unsigned           g_umax[ROWS_];    // per-row fg-score ord bits
__device__ unsigned           g_keyhi[ROWS_];   // key high word (low word = ~r)
__device__ signed char        g_conf[ROWS_];
__device__ int                g_hist0[2048];
__device__ int                g_hist1[2048];
__device__ unsigned long long g_cand[CAND_CAP];
__device__ unsigned long long g_cand2[CAND2_CAP];
__device__ int                g_cand_cnt;
__device__ int                g_cand2_cnt;
__device__ int                g_work[ROWS_];    // (r<<8) | target
__device__ int                g_work_cnt;
__device__ int                g_num_pos;
__device__ int                g_K;
__device__ int                g_d1;
__device__ long long          g_Krem1;
__device__ int                g_d2;
__device__ long long          g_Krem2;
__device__ float              g_sl1;
__device__ float              g_ce_sum;
__device__ int                g_done_match;
__device__ int                g_done_tail;
__device__ int                g_done_s1;
__device__ int                g_done_s2;
__device__ int                g_done_ce;
__device__ int                g_seeded;         // 0 on first run: seed gt_best

__device__ __forceinline__ float smooth_l1(float d) {
    float ad = fabsf(d);
    return ad < 1.f ? 0.5f * d * d : ad - 0.5f;
}
__device__ __forceinline__ unsigned ord_bits(float x) {
    unsigned b = __float_as_uint(x);
    unsigned m = (unsigned)((int)b >> 31) | 0x80000000u;
    return b ^ m;   // monotonic float -> uint
}
__device__ __forceinline__ unsigned long long full_key(unsigned u, int r) {
    return (((unsigned long long)u) << 32) | (unsigned)(~(unsigned)r);
}

// warp-aggregated append (call from ALL lanes, uniform control flow)
__device__ __forceinline__ int warp_append(int* ctr, bool pred) {
    unsigned bal = __ballot_sync(0xffffffffu, pred);
    int lane = threadIdx.x & 31;
    int base = 0;
    int leader = __ffs(bal) - 1;
    if (bal && lane == leader) base = atomicAdd(ctr, __popc(bal));
    base = __shfl_sync(0xffffffffu, base, leader < 0 ? 0 : leader);
    return base + __popc(bal & ((1u << lane) - 1u));
}

// suffix-scan pick over 2048 buckets, 256 threads.
__device__ void pick_digit(const int* hist, long long Krem_in,
                           int& d_out, long long& Krem_out) {
    __shared__ long long suf[256];
    __shared__ int s_d;
    __shared__ long long s_k;
    int t = threadIdx.x;
    int h[8];
    long long s = 0;
    #pragma unroll
    for (int i = 0; i < 8; i++) { h[i] = hist[t * 8 + i]; s += h[i]; }
    suf[t] = s;
    __syncthreads();
    #pragma unroll
    for (int off = 1; off < 256; off <<= 1) {
        long long v = (t + off < 256) ? suf[t + off] : 0;
        __syncthreads();
        suf[t] += v;
        __syncthreads();
    }
    long long above = (t + 1 < 256) ? suf[t + 1] : 0;
    if (suf[t] >= Krem_in && above < Krem_in) {
        long long ab = above;
        int d = t * 8;
        #pragma unroll
        for (int i = 7; i >= 0; i--) {
            if (ab + h[i] >= Krem_in) { d = t * 8 + i; break; }
            ab += h[i];
        }
        s_d = d; s_k = Krem_in - ab;
    }
    __syncthreads();
    d_out = s_d;
    Krem_out = s_k;
}

// ---------------- K-A: pure conf max-scan (150 MB, NO dependencies) ----------
__global__ void __launch_bounds__(256, 8)
k_max(const float* __restrict__ conf_data) {
    const float NINF = __int_as_float(0xff800000);
    const int lane = threadIdx.x & 31;
    const int wid  = (blockIdx.x * blockDim.x + threadIdx.x) >> 5;
    const int nw   = (gridDim.x * blockDim.x) >> 5;
    const int NCH = ROWS_ / 8;

    for (int ch = wid; ch < NCH; ch += nw) {
        const float* base = conf_data + (size_t)(ch * 8) * C_;
        float fr[8];
        #pragma unroll
        for (int j = 0; j < 8; j++) {
            const float* row = base + j * C_;
            float a  = __ldcs(row + lane);
            float b2 = __ldcs(row + lane + 32);
            float c2 = (lane < 17) ? __ldcs(row + lane + 64) : NINF;
            fr[j] = fmaxf(fmaxf(lane ? a : NINF, b2), c2);
        }
        unsigned mr[8];
        #pragma unroll
        for (int j = 0; j < 8; j++)
            mr[j] = __reduce_max_sync(0xffffffffu, ord_bits(fr[j]));
        if (lane < 8) {
            unsigned uu = (lane & 4)
                ? ((lane & 2) ? ((lane & 1) ? mr[7] : mr[6])
                              : ((lane & 1) ? mr[5] : mr[4]))
                : ((lane & 2) ? ((lane & 1) ? mr[3] : mr[2])
                              : ((lane & 1) ? mr[1] : mr[0]));
            g_umax[ch * 8 + lane] = uu;
        }
    }
}

// ---------------- K-B: matching + (last block) force-patch (side stream) -----
__global__ void k_match(const float* __restrict__ priors,
                        const float* __restrict__ gt_boxes) {
    int b = blockIdx.y;
    int p = blockIdx.x * 256 + threadIdx.x;

    __shared__ float4 s_gt[N_];
    __shared__ float  s_area[N_];
    __shared__ unsigned long long s_best[N_];
    if (blockIdx.x == 0 && blockIdx.y == 0 && threadIdx.x == 0) {
        if (atomicExch(&g_seeded, 1) == 0) {
            for (int i = 0; i < B_ * N_; i++)
                atomicMax(&g_gt_best[i], 0x00000000FFFFFFFFull);
        }
    }
    if (threadIdx.x < N_) {
        float4 g = reinterpret_cast<const float4*>(gt_boxes)[b * N_ + threadIdx.x];
        s_gt[threadIdx.x] = g;
        s_area[threadIdx.x] = (g.z - g.x) * (g.w - g.y);
        s_best[threadIdx.x] = 0x00000000FFFFFFFFull;  // fallback prior 0
    }
    __syncthreads();

    if (p < P_) {
        float4 pr = reinterpret_cast<const float4*>(priors)[p];
        float px1 = pr.x - pr.z * 0.5f, py1 = pr.y - pr.w * 0.5f;
        float px2 = pr.x + pr.z * 0.5f, py2 = pr.y + pr.w * 0.5f;
        float parea = (px2 - px1) * (py2 - py1);

        float best = 0.f; int bestn = 0;
        #pragma unroll
        for (int n = 0; n < N_; n++) {
            float4 g = s_gt[n];
            float ix1 = fmaxf(px1, g.x), iy1 = fmaxf(py1, g.y);
            float ix2 = fminf(px2, g.z), iy2 = fminf(py2, g.w);
            float iw = fmaxf(ix2 - ix1, 0.f), ih = fmaxf(iy2 - iy1, 0.f);
            float inter = iw * ih;
            float iou = inter / (s_area[n] + parea - inter);
            if (iou > best) { best = iou; bestn = n; }
            if (inter > 0.f) {
                unsigned long long key =
                    (((unsigned long long)__float_as_uint(iou)) << 32) |
                    (unsigned)(~(unsigned)p);
                atomicMax(&s_best[n], key);
            }
        }
        int band = (best < NEG_TH) ? 0 : ((best < POS_TH) ? 1 : 2);
        g_mt[b * P_ + p] = (unsigned char)((bestn << 2) | band);
    }
    __syncthreads();
    if (threadIdx.x < N_)
        atomicMax(&g_gt_best[b * N_ + threadIdx.x], s_best[threadIdx.x]);

    // last block patches forced matches into g_mt (band 3, last-GT-wins)
    __shared__ int s_last;
    __threadfence();
    __syncthreads();
    if (threadIdx.x == 0)
        s_last = (atomicAdd(&g_done_match, 1) ==
                  (int)(gridDim.x * gridDim.y) - 1);
    __syncthreads();
    if (!s_last) return;
    int w  = threadIdx.x >> 5;    // 8 warps = 8 batches
    int ln = threadIdx.x & 31;
    if (ln < N_) {
        unsigned long long key = g_gt_best[w * N_ + ln];
        unsigned p2 = ~(unsigned)(key & 0xFFFFFFFFull);
        unsigned msk = __match_any_sync(0xFFFFFu, p2);
        int winner = 31 - __clz((int)msk);   // highest n among dup priors
        if (ln == winner)
            g_mt[w * P_ + p2] = (unsigned char)((ln << 2) | 3);
    }
}

// ---------------- K-C: tail: conf/keyhi/hist0/loc-loss + pick d1 -------------
__global__ void __launch_bounds__(256)
k_tail(const float* __restrict__ loc_data,
       const float* __restrict__ priors,
       const float* __restrict__ gt_boxes,
       const int* __restrict__ gt_labels) {
    __shared__ int s_hist[2048];
    __shared__ int s_labels[B_ * N_];
    for (int i = threadIdx.x; i < 2048; i += 256) s_hist[i] = 0;
    if (threadIdx.x < B_ * N_) s_labels[threadIdx.x] = gt_labels[threadIdx.x];
    __syncthreads();

    const int lane = threadIdx.x & 31;
    float lsl = 0.f;
    int t = blockIdx.x * 256 + threadIdx.x;
    int stride = gridDim.x * 256;

    for (int r = t; r < ROWS_; r += stride) {
        unsigned uu = g_umax[r];
        unsigned mt = g_mt[r];
        int b = r / P_;
        int band = mt & 3;
        int n = mt >> 2;
        int c = (band == 0) ? 0 : ((band == 1) ? -1 : s_labels[b * N_ + n]);
        g_conf[r] = (signed char)c;
        unsigned u = (c == 0) ? uu : 0u;
        g_keyhi[r] = u;
        atomicAdd(&s_hist[(int)(u >> 21)], 1);
        if (c > 0) {
            int p = r - b * P_;
            float4 pr = reinterpret_cast<const float4*>(priors)[p];
            float4 g  = reinterpret_cast<const float4*>(gt_boxes)[b * N_ + n];
            float4 ld = reinterpret_cast<const float4*>(loc_data)[r];
            float tx = ((g.x + g.z) * 0.5f - pr.x) / (0.1f * pr.z);
            float ty = ((g.y + g.w) * 0.5f - pr.y) / (0.1f * pr.w);
            float tw = logf((g.z - g.x) / pr.z) * 5.0f;
            float th = logf((g.w - g.y) / pr.w) * 5.0f;
            lsl += smooth_l1(ld.x - tx) + smooth_l1(ld.y - ty)
                 + smooth_l1(ld.z - tw) + smooth_l1(ld.w - th);
            int pos = atomicAdd(&g_work_cnt, 1);   // ~700 total: cheap
            g_work[pos] = (r << 8) | c;
        }
    }

    #pragma unroll
    for (int o = 16; o; o >>= 1) lsl += __shfl_xor_sync(0xffffffffu, lsl, o);
    __shared__ float sf[8];
    int w = threadIdx.x >> 5;
    if (lane == 0) sf[w] = lsl;
    __syncthreads();
    if (threadIdx.x == 0) {
        float a = 0.f;
        #pragma unroll
        for (int i = 0; i < 8; i++) a += sf[i];
        if (a != 0.f) atomicAdd(&g_sl1, a);
    }
    __syncthreads();
    for (int i = threadIdx.x; i < 2048; i += 256) {
        int v = s_hist[i];
        if (v) atomicAdd(&g_hist0[i], v);
    }

    // last block: num_pos from worklist (all entries are positives), pick d1
    __shared__ int s_last;
    __threadfence();
    if (threadIdx.x == 0)
        s_last = (atomicAdd(&g_done_tail, 1) == (int)gridDim.x - 1);
    __syncthreads();
    if (!s_last) return;
    int np = g_work_cnt;
    long long K = 3LL * np;
    if (K > ROWS_) K = ROWS_;
    if (threadIdx.x == 0) { g_num_pos = np; g_K = (int)K; }
    if (K == 0) return;
    int d1; long long kr;
    pick_digit(g_hist0, K, d1, kr);
    if (threadIdx.x == 0) { g_d1 = d1; g_Krem1 = kr; }
}

// ---------------- K3: u32 key scan (4/thread) + hist1 + pick d2 --------------
__global__ void __launch_bounds__(256) k_scan1() {
    if (g_K == 0) return;
    const unsigned D1 = (unsigned)g_d1;
    __shared__ int sh[2048];
    for (int i = threadIdx.x; i < 2048; i += 256) sh[i] = 0;
    __syncthreads();

    int i = blockIdx.x * 256 + threadIdx.x;
    bool in = (i < ROWS_ / 4);
    uint4 kk = in ? reinterpret_cast<const uint4*>(g_keyhi)[i]
                  : make_uint4(0, 0, 0, 0);
    #pragma unroll
    for (int j = 0; j < 4; j++) {
        unsigned u = j == 0 ? kk.x : j == 1 ? kk.y : j == 2 ? kk.z : kk.w;
        int r = i * 4 + j;
        unsigned d = u >> 21;
        bool is_cand = in && (d == D1);
        bool is_keep = in && (d > D1);
        if (is_cand) atomicAdd(&sh[(int)((u >> 10) & 2047)], 1);
        int cslot = warp_append(&g_cand_cnt, is_cand);
        if (is_cand && cslot < CAND_CAP) g_cand[cslot] = full_key(u, r);
        int kslot = warp_append(&g_work_cnt, is_keep);
        if (is_keep) g_work[kslot] = r << 8;
    }
    __syncthreads();
    for (int i2 = threadIdx.x; i2 < 2048; i2 += 256) {
        int v = sh[i2];
        if (v) atomicAdd(&g_hist1[i2], v);
    }

    __shared__ int s_last;
    __threadfence();
    if (threadIdx.x == 0)
        s_last = (atomicAdd(&g_done_s1, 1) == (int)gridDim.x - 1);
    __syncthreads();
    if (!s_last) return;
    int d2; long long kr;
    pick_digit(g_hist1, g_Krem1, d2, kr);
    if (threadIdx.x == 0) { g_d2 = d2; g_Krem2 = kr; }
}

// ---------------- K4: cand scan + last-block exact resolve -------------------
__global__ void __launch_bounds__(256) k_scan2() {
    if (g_K == 0) return;
    const unsigned long long D2 = (unsigned long long)g_d2;
    int cnt = g_cand_cnt;
    if (cnt > CAND_CAP) cnt = CAND_CAP;

    int t = blockIdx.x * 256 + threadIdx.x;
    int stride = gridDim.x * 256;
    int iters = (cnt + stride - 1) / stride;
    for (int it = 0; it < iters; it++) {
        int i = t + it * stride;
        bool in = (i < cnt);
        unsigned long long key = in ? g_cand[i] : 0ull;
        unsigned long long mid = (key >> 42) & 2047;
        bool is_tie = in && (mid == D2);
        bool pre    = in && (mid > D2);
        int r = pre ? (int)(~(unsigned)(key & 0xFFFFFFFFull)) : 0;
        bool is_keep = pre && (g_conf[r] == 0);
        int cslot = warp_append(&g_cand2_cnt, is_tie);
        if (is_tie && cslot < CAND2_CAP) g_cand2[cslot] = key;
        int kslot = warp_append(&g_work_cnt, is_keep);
        if (is_keep) g_work[kslot] = r << 8;
    }

    // last block: exact resolve of remaining 42 bits (warp 0)
    __shared__ int s_last;
    __shared__ unsigned long long s_cand[SM_CAND];
    __threadfence();
    if (threadIdx.x == 0)
        s_last = (atomicAdd(&g_done_s2, 1) == (int)gridDim.x - 1);
    __syncthreads();
    if (!s_last) return;

    int c2 = g_cand2_cnt;
    if (c2 > CAND2_CAP) c2 = CAND2_CAP;
    bool in_sm = (c2 <= SM_CAND);
    if (in_sm)
        for (int i = threadIdx.x; i < c2; i += 256) s_cand[i] = g_cand2[i];
    __syncthreads();
    if (threadIdx.x >= 32) return;

    int lane = threadIdx.x;
    unsigned long long F =
        (((unsigned long long)g_d1) << 11) | (unsigned long long)g_d2;
    long long Kr = g_Krem2;
    for (int b = 41; b >= 0; b--) {
        int local = 0;
        for (int i = lane; i < c2; i += 32) {
            unsigned long long k2 = in_sm ? s_cand[i] : g_cand2[i];
            if ((k2 >> (b + 1)) == F && ((k2 >> b) & 1ull)) local++;
        }
        int c1 = __reduce_add_sync(0xffffffffu, local);
        if (c1 >= Kr) F = (F << 1) | 1ull;
        else { Kr -= c1; F <<= 1; }
    }
    for (int i = lane; i < c2; i += 32) {
        unsigned long long k2 = in_sm ? s_cand[i] : g_cand2[i];
        if (k2 >= F) {
            int r = (int)(~(unsigned)(k2 & 0xFFFFFFFFull));
            if (g_conf[r] == 0) {
                int pos = atomicAdd(&g_work_cnt, 1);
                g_work[pos] = r << 8;
            }
        }
    }
}

// ---------------- K5: CE over worklist + output + state reset ----------------
__global__ void __launch_bounds__(256)
k_ce(const float* __restrict__ conf_data, float* __restrict__ out) {
    const float NINF = __int_as_float(0xff800000);
    const int lane = threadIdx.x & 31;
    const int wid  = (blockIdx.x * blockDim.x + threadIdx.x) >> 5;
    const int nw   = (gridDim.x * blockDim.x) >> 5;
    int cnt = g_work_cnt;
    float lce = 0.f;

    // early blocks reset histograms + gt_best for the NEXT replay
    {
        int t = blockIdx.x * 256 + threadIdx.x;
        if (t < 2048) { g_hist0[t] = 0; g_hist1[t] = 0; }
        if (t >= 2048 && t < 2048 + B_ * N_)
            g_gt_best[t - 2048] = 0x00000000FFFFFFFFull;
    }

    for (int i = wid; i < cnt; i += nw) {
        int item = g_work[i];
        int r  = item >> 8;
        int ct = item & 255;
        const float* row = conf_data + (size_t)r * C_;
        float x0 = row[lane];
        float x1 = row[lane + 32];
        float x2 = (lane < 17) ? row[lane + 64] : NINF;
        float m = fmaxf(x0, fmaxf(x1, x2));
        #pragma unroll
        for (int o = 16; o; o >>= 1)
            m = fmaxf(m, __shfl_xor_sync(0xffffffffu, m, o));
        float s = expf(x0 - m) + expf(x1 - m) + ((lane < 17) ? expf(x2 - m) : 0.f);
        #pragma unroll
        for (int o = 16; o; o >>= 1) s += __shfl_xor_sync(0xffffffffu, s, o);
        float tv = NINF;
        if (lane == ct)                   tv = x0;
        if (lane + 32 == ct)              tv = x1;
        if (lane < 17 && lane + 64 == ct) tv = x2;
        #pragma unroll
        for (int o = 16; o; o >>= 1)
            tv = fmaxf(tv, __shfl_xor_sync(0xffffffffu, tv, o));
        if (lane == 0) lce += (m + logf(s)) - tv;
    }

    #pragma unroll
    for (int o = 16; o; o >>= 1) lce += __shfl_xor_sync(0xffffffffu, lce, o);
    __shared__ float sf[8];
    int w = threadIdx.x >> 5;
    if (lane == 0) sf[w] = lce;
    __syncthreads();
    if (threadIdx.x == 0) {
        float a = 0.f;
        #pragma unroll
        for (int i = 0; i < 8; i++) a += sf[i];
        if (a != 0.f) atomicAdd(&g_ce_sum, a);
        __threadfence();
        int done = atomicAdd(&g_done_ce, 1);
        if (done == (int)gridDim.x - 1) {
            int np = g_num_pos; if (np < 1) np = 1;
            int kp = cnt;       if (kp < 1) kp = 1;
            out[0] = g_sl1    / (float)np;
            out[1] = g_ce_sum / (float)kp;
            // ---- reset remaining state for next replay ----
            g_sl1 = 0.f; g_ce_sum = 0.f;
            g_work_cnt = 0; g_cand_cnt = 0; g_cand2_cnt = 0;
            g_num_pos = 0; g_K = 0;
            g_done_match = 0; g_done_tail = 0; g_done_s1 = 0;
            g_done_s2 = 0; g_done_ce = 0;
            __threadfence();
        }
    }
}

// ---------------- host -------------------------------------------------------
extern "C" void kernel_launch(void* const* d_in, const int* in_sizes, int n_in,
                              void* d_out, int out_size) {
    const float* loc = nullptr;
    const float* conf = nullptr;
    const float* priors = nullptr;
    const float* gtb = nullptr;
    const int*   gtl = nullptr;
    for (int i = 0; i < n_in; i++) {
        long long s = in_sizes[i];
        if      (s == (long long)B_ * P_ * C_) conf   = (const float*)d_in[i];
        else if (s == (long long)B_ * P_ * 4)  loc    = (const float*)d_in[i];
        else if (s == (long long)P_ * 4)       priors = (const float*)d_in[i];
        else if (s == (long long)B_ * N_ * 4)  gtb    = (const float*)d_in[i];
        else if (s == (long long)B_ * N_)      gtl    = (const int*)d_in[i];
    }
    float* out = (float*)d_out;

    // capture-safe stream fork: k_match (side) overlaps k_max (main)
    static cudaStream_t s_side = nullptr;
    static cudaEvent_t  e_fork = nullptr, e_join = nullptr;
    if (!s_side) {
        cudaStreamCreateWithFlags(&s_side, cudaStreamNonBlocking);
        cudaEventCreateWithFlags(&e_fork, cudaEventDisableTiming);
        cudaEventCreateWithFlags(&e_join, cudaEventDisableTiming);
    }

    cudaEventRecord(e_fork, 0);
    cudaStreamWaitEvent(s_side, e_fork, 0);
    k_match<<<dim3((P_ + 255) / 256, B_), 256, 0, s_side>>>(priors, gtb);
    cudaEventRecord(e_join, s_side);

    k_max<<<1776, 256>>>(conf);          // concurrent with k_match

    cudaStreamWaitEvent(0, e_join, 0);   // join before tail
    k_tail<<<904, 256>>>(loc, priors, gtb, gtl);
    k_scan1<<<452, 256>>>();
    k_scan2<<<592, 256>>>();
    k_ce<<<464, 256>>>(conf, out);
}

// round 15
// speedup vs baseline: 2.4144x; 1.0651x over previous
#include <cuda_runtime.h>

#define B_ 8
#define P_ 57744
#define C_ 81
#define N_ 20
#define ROWS_ (B_ * P_)
#define POS_TH 0.5f
#define NEG_TH 0.4f
#define CAND_CAP 131072
#define CAND2_CAP 16384
#define SM_CAND 2048

// ---------------- scratch (static __device__, zero-init at load) -------------
// Self-cleaning pipeline: k_ce resets everything for the next replay.
__device__ unsigned char      g_mt[ROWS_];      // (gt_idx<<2)|band; band3=forced
__device__ unsigned long long g_gt_best[B_ * N_];
__device__ unsigned           g_umax[ROWS_];    // per-row fg-score ord bits
__device__ unsigned           g_keyhi[ROWS_];   // key high word (low word = ~r)
__device__ signed char        g_conf[ROWS_];
__device__ int                g_hist0[2048];
__device__ int                g_hist1[2048];
__device__ unsigned long long g_cand[CAND_CAP];
__device__ unsigned long long g_cand2[CAND2_CAP];
__device__ int                g_cand_cnt;
__device__ int                g_cand2_cnt;
__device__ int                g_work[ROWS_];    // (r<<8) | target
__device__ int                g_work_cnt;
__device__ int                g_num_pos;
__device__ int                g_K;
__device__ int                g_d1;
__device__ long long          g_Krem1;
__device__ int                g_d2;
__device__ long long          g_Krem2;
__device__ float              g_sl1;
__device__ float              g_ce_sum;
__device__ int                g_done_match;
__device__ int                g_done_tail;
__device__ int                g_done_s1;
__device__ int                g_done_s2;
__device__ int                g_done_ce;
__device__ int                g_seeded;         // 0 on first run: seed gt_best

__device__ __forceinline__ float smooth_l1(float d) {
    float ad = fabsf(d);
    return ad < 1.f ? 0.5f * d * d : ad - 0.5f;
}
__device__ __forceinline__ unsigned ord_bits(float x) {
    unsigned b = __float_as_uint(x);
    unsigned m = (unsigned)((int)b >> 31) | 0x80000000u;
    return b ^ m;   // monotonic float -> uint
}
__device__ __forceinline__ unsigned long long full_key(unsigned u, int r) {
    return (((unsigned long long)u) << 32) | (unsigned)(~(unsigned)r);
}

// suffix-scan pick over 2048 buckets, 256 threads.
__device__ void pick_digit(const int* hist, long long Krem_in,
                           int& d_out, long long& Krem_out) {
    __shared__ long long suf[256];
    __shared__ int s_d;
    __shared__ long long s_k;
    int t = threadIdx.x;
    int h[8];
    long long s = 0;
    #pragma unroll
    for (int i = 0; i < 8; i++) { h[i] = hist[t * 8 + i]; s += h[i]; }
    suf[t] = s;
    __syncthreads();
    #pragma unroll
    for (int off = 1; off < 256; off <<= 1) {
        long long v = (t + off < 256) ? suf[t + off] : 0;
        __syncthreads();
        suf[t] += v;
        __syncthreads();
    }
    long long above = (t + 1 < 256) ? suf[t + 1] : 0;
    if (suf[t] >= Krem_in && above < Krem_in) {
        long long ab = above;
        int d = t * 8;
        #pragma unroll
        for (int i = 7; i >= 0; i--) {
            if (ab + h[i] >= Krem_in) { d = t * 8 + i; break; }
            ab += h[i];
        }
        s_d = d; s_k = Krem_in - ab;
    }
    __syncthreads();
    d_out = s_d;
    Krem_out = s_k;
}

// ---------------- K-A: pure conf max-scan (150 MB, NO dependencies) ----------
__global__ void __launch_bounds__(256, 8)
k_max(const float* __restrict__ conf_data) {
    const float NINF = __int_as_float(0xff800000);
    const int lane = threadIdx.x & 31;
    const int wid  = (blockIdx.x * blockDim.x + threadIdx.x) >> 5;
    const int nw   = (gridDim.x * blockDim.x) >> 5;
    const int NCH = ROWS_ / 8;

    for (int ch = wid; ch < NCH; ch += nw) {
        const float* base = conf_data + (size_t)(ch * 8) * C_;
        float fr[8];
        #pragma unroll
        for (int j = 0; j < 8; j++) {
            const float* row = base + j * C_;
            float a  = __ldcs(row + lane);
            float b2 = __ldcs(row + lane + 32);
            float c2 = (lane < 17) ? __ldcs(row + lane + 64) : NINF;
            fr[j] = fmaxf(fmaxf(lane ? a : NINF, b2), c2);
        }
        unsigned mr[8];
        #pragma unroll
        for (int j = 0; j < 8; j++)
            mr[j] = __reduce_max_sync(0xffffffffu, ord_bits(fr[j]));
        if (lane < 8) {
            unsigned uu = (lane & 4)
                ? ((lane & 2) ? ((lane & 1) ? mr[7] : mr[6])
                              : ((lane & 1) ? mr[5] : mr[4]))
                : ((lane & 2) ? ((lane & 1) ? mr[3] : mr[2])
                              : ((lane & 1) ? mr[1] : mr[0]));
            g_umax[ch * 8 + lane] = uu;
        }
    }
}

// ---------------- K-B: matching + (last block) force-patch (side stream) -----
__global__ void k_match(const float* __restrict__ priors,
                        const float* __restrict__ gt_boxes) {
    int b = blockIdx.y;
    int p = blockIdx.x * 256 + threadIdx.x;

    __shared__ float4 s_gt[N_];
    __shared__ float  s_area[N_];
    __shared__ unsigned long long s_best[N_];
    if (blockIdx.x == 0 && blockIdx.y == 0 && threadIdx.x == 0) {
        if (atomicExch(&g_seeded, 1) == 0) {
            for (int i = 0; i < B_ * N_; i++)
                atomicMax(&g_gt_best[i], 0x00000000FFFFFFFFull);
        }
    }
    if (threadIdx.x < N_) {
        float4 g = reinterpret_cast<const float4*>(gt_boxes)[b * N_ + threadIdx.x];
        s_gt[threadIdx.x] = g;
        s_area[threadIdx.x] = (g.z - g.x) * (g.w - g.y);
        s_best[threadIdx.x] = 0x00000000FFFFFFFFull;  // fallback prior 0
    }
    __syncthreads();

    if (p < P_) {
        float4 pr = reinterpret_cast<const float4*>(priors)[p];
        float px1 = pr.x - pr.z * 0.5f, py1 = pr.y - pr.w * 0.5f;
        float px2 = pr.x + pr.z * 0.5f, py2 = pr.y + pr.w * 0.5f;
        float parea = (px2 - px1) * (py2 - py1);

        float best = 0.f; int bestn = 0;
        #pragma unroll
        for (int n = 0; n < N_; n++) {
            float4 g = s_gt[n];
            float ix1 = fmaxf(px1, g.x), iy1 = fmaxf(py1, g.y);
            float ix2 = fminf(px2, g.z), iy2 = fminf(py2, g.w);
            float iw = fmaxf(ix2 - ix1, 0.f), ih = fmaxf(iy2 - iy1, 0.f);
            float inter = iw * ih;
            float iou = inter / (s_area[n] + parea - inter);
            if (iou > best) { best = iou; bestn = n; }
            if (inter > 0.f) {
                unsigned long long key =
                    (((unsigned long long)__float_as_uint(iou)) << 32) |
                    (unsigned)(~(unsigned)p);
                atomicMax(&s_best[n], key);
            }
        }
        int band = (best < NEG_TH) ? 0 : ((best < POS_TH) ? 1 : 2);
        g_mt[b * P_ + p] = (unsigned char)((bestn << 2) | band);
    }
    __syncthreads();
    if (threadIdx.x < N_)
        atomicMax(&g_gt_best[b * N_ + threadIdx.x], s_best[threadIdx.x]);

    // last block patches forced matches into g_mt (band 3, last-GT-wins)
    __shared__ int s_last;
    __threadfence();
    __syncthreads();
    if (threadIdx.x == 0)
        s_last = (atomicAdd(&g_done_match, 1) ==
                  (int)(gridDim.x * gridDim.y) - 1);
    __syncthreads();
    if (!s_last) return;
    int w  = threadIdx.x >> 5;    // 8 warps = 8 batches
    int ln = threadIdx.x & 31;
    if (ln < N_) {
        unsigned long long key = g_gt_best[w * N_ + ln];
        unsigned p2 = ~(unsigned)(key & 0xFFFFFFFFull);
        unsigned msk = __match_any_sync(0xFFFFFu, p2);
        int winner = 31 - __clz((int)msk);   // highest n among dup priors
        if (ln == winner)
            g_mt[w * P_ + p2] = (unsigned char)((ln << 2) | 3);
    }
}

// ---------------- K-C: tail: conf/keyhi/hist0/loc-loss + pick d1 -------------
__global__ void __launch_bounds__(256)
k_tail(const float* __restrict__ loc_data,
       const float* __restrict__ priors,
       const float* __restrict__ gt_boxes,
       const int* __restrict__ gt_labels) {
    __shared__ int s_hist[2048];
    __shared__ int s_labels[B_ * N_];
    for (int i = threadIdx.x; i < 2048; i += 256) s_hist[i] = 0;
    if (threadIdx.x < B_ * N_) s_labels[threadIdx.x] = gt_labels[threadIdx.x];
    __syncthreads();

    const int lane = threadIdx.x & 31;
    float lsl = 0.f;
    int t = blockIdx.x * 256 + threadIdx.x;
    int stride = gridDim.x * 256;

    for (int r = t; r < ROWS_; r += stride) {
        unsigned uu = g_umax[r];
        unsigned mt = g_mt[r];
        int b = r / P_;
        int band = mt & 3;
        int n = mt >> 2;
        int c = (band == 0) ? 0 : ((band == 1) ? -1 : s_labels[b * N_ + n]);
        g_conf[r] = (signed char)c;
        unsigned u = (c == 0) ? uu : 0u;
        g_keyhi[r] = u;
        atomicAdd(&s_hist[(int)(u >> 21)], 1);
        if (c > 0) {
            int p = r - b * P_;
            float4 pr = reinterpret_cast<const float4*>(priors)[p];
            float4 g  = reinterpret_cast<const float4*>(gt_boxes)[b * N_ + n];
            float4 ld = reinterpret_cast<const float4*>(loc_data)[r];
            float tx = ((g.x + g.z) * 0.5f - pr.x) / (0.1f * pr.z);
            float ty = ((g.y + g.w) * 0.5f - pr.y) / (0.1f * pr.w);
            float tw = logf((g.z - g.x) / pr.z) * 5.0f;
            float th = logf((g.w - g.y) / pr.w) * 5.0f;
            lsl += smooth_l1(ld.x - tx) + smooth_l1(ld.y - ty)
                 + smooth_l1(ld.z - tw) + smooth_l1(ld.w - th);
            int pos = atomicAdd(&g_work_cnt, 1);   // ~700 total: cheap
            g_work[pos] = (r << 8) | c;
        }
    }

    #pragma unroll
    for (int o = 16; o; o >>= 1) lsl += __shfl_xor_sync(0xffffffffu, lsl, o);
    __shared__ float sf[8];
    int w = threadIdx.x >> 5;
    if (lane == 0) sf[w] = lsl;
    __syncthreads();
    if (threadIdx.x == 0) {
        float a = 0.f;
        #pragma unroll
        for (int i = 0; i < 8; i++) a += sf[i];
        if (a != 0.f) atomicAdd(&g_sl1, a);
    }
    __syncthreads();
    for (int i = threadIdx.x; i < 2048; i += 256) {
        int v = s_hist[i];
        if (v) atomicAdd(&g_hist0[i], v);
    }

    // last block: num_pos from worklist (all entries are positives), pick d1
    __shared__ int s_last;
    __threadfence();
    if (threadIdx.x == 0)
        s_last = (atomicAdd(&g_done_tail, 1) == (int)gridDim.x - 1);
    __syncthreads();
    if (!s_last) return;
    int np = g_work_cnt;
    long long K = 3LL * np;
    if (K > ROWS_) K = ROWS_;
    if (threadIdx.x == 0) { g_num_pos = np; g_K = (int)K; }
    if (K == 0) return;
    int d1; long long kr;
    pick_digit(g_hist0, K, d1, kr);
    if (threadIdx.x == 0) { g_d1 = d1; g_Krem1 = kr; }
}

// ---------------- K3: key scan, SMEM-STAGED appends + hist1 + pick d2 --------
#define S1_STC 2048
#define S1_STK 1024
__global__ void __launch_bounds__(256) k_scan1() {
    if (g_K == 0) return;
    const unsigned D1 = (unsigned)g_d1;
    __shared__ int sh[2048];
    __shared__ unsigned long long st_c[S1_STC];
    __shared__ int st_k[S1_STK];
    __shared__ int s_nc, s_nk, s_bc, s_bk;
    for (int i = threadIdx.x; i < 2048; i += 256) sh[i] = 0;
    if (threadIdx.x == 0) { s_nc = 0; s_nk = 0; }
    __syncthreads();

    int i = blockIdx.x * 256 + threadIdx.x;
    bool in = (i < ROWS_ / 4);
    uint4 kk = in ? reinterpret_cast<const uint4*>(g_keyhi)[i]
                  : make_uint4(0, 0, 0, 0);
    #pragma unroll
    for (int j = 0; j < 4; j++) {
        unsigned u = j == 0 ? kk.x : j == 1 ? kk.y : j == 2 ? kk.z : kk.w;
        int r = i * 4 + j;
        unsigned d = u >> 21;
        if (in && d == D1) {
            atomicAdd(&sh[(int)((u >> 10) & 2047)], 1);
            int s = atomicAdd(&s_nc, 1);
            if (s < S1_STC) st_c[s] = full_key(u, r);
            else {  // overflow (shouldn't happen: <=1024 rows/block)
                int g2 = atomicAdd(&g_cand_cnt, 1);
                if (g2 < CAND_CAP) g_cand[g2] = full_key(u, r);
            }
        } else if (in && d > D1) {
            int s = atomicAdd(&s_nk, 1);
            if (s < S1_STK) st_k[s] = r << 8;
            else g_work[atomicAdd(&g_work_cnt, 1)] = r << 8;
        }
    }
    __syncthreads();
    int c  = s_nc < S1_STC ? s_nc : S1_STC;
    int k2 = s_nk < S1_STK ? s_nk : S1_STK;
    if (threadIdx.x == 0) {
        s_bc = c  ? atomicAdd(&g_cand_cnt, c)  : 0;
        s_bk = k2 ? atomicAdd(&g_work_cnt, k2) : 0;
    }
    __syncthreads();
    for (int t2 = threadIdx.x; t2 < c; t2 += 256) {
        int pos = s_bc + t2;
        if (pos < CAND_CAP) g_cand[pos] = st_c[t2];
    }
    for (int t2 = threadIdx.x; t2 < k2; t2 += 256)
        g_work[s_bk + t2] = st_k[t2];
    for (int i2 = threadIdx.x; i2 < 2048; i2 += 256) {
        int v = sh[i2];
        if (v) atomicAdd(&g_hist1[i2], v);
    }

    __shared__ int s_last;
    __threadfence();
    if (threadIdx.x == 0)
        s_last = (atomicAdd(&g_done_s1, 1) == (int)gridDim.x - 1);
    __syncthreads();
    if (!s_last) return;
    int d2; long long kr;
    pick_digit(g_hist1, g_Krem1, d2, kr);
    if (threadIdx.x == 0) { g_d2 = d2; g_Krem2 = kr; }
}

// ---------------- K4: cand scan, SMEM-STAGED + last-block exact resolve ------
#define S2_ST 512
__global__ void __launch_bounds__(256) k_scan2() {
    if (g_K == 0) return;
    const unsigned long long D2 = (unsigned long long)g_d2;
    int cnt = g_cand_cnt;
    if (cnt > CAND_CAP) cnt = CAND_CAP;

    __shared__ unsigned long long st_c[S2_ST];
    __shared__ int st_k[S2_ST];
    __shared__ int s_nc, s_nk, s_bc, s_bk;
    if (threadIdx.x == 0) { s_nc = 0; s_nk = 0; }
    __syncthreads();

    int t = blockIdx.x * 256 + threadIdx.x;
    int stride = gridDim.x * 256;
    int iters = (cnt + stride - 1) / stride;
    for (int it = 0; it < iters; it++) {
        int i = t + it * stride;
        bool in = (i < cnt);
        unsigned long long key = in ? g_cand[i] : 0ull;
        unsigned long long mid = (key >> 42) & 2047;
        if (in && mid == D2) {
            int s = atomicAdd(&s_nc, 1);
            if (s < S2_ST) st_c[s] = key;
            else {
                int g2 = atomicAdd(&g_cand2_cnt, 1);
                if (g2 < CAND2_CAP) g_cand2[g2] = key;
            }
        } else if (in && mid > D2) {
            int r = (int)(~(unsigned)(key & 0xFFFFFFFFull));
            if (g_conf[r] == 0) {
                int s = atomicAdd(&s_nk, 1);
                if (s < S2_ST) st_k[s] = r << 8;
                else g_work[atomicAdd(&g_work_cnt, 1)] = r << 8;
            }
        }
    }
    __syncthreads();
    int c  = s_nc < S2_ST ? s_nc : S2_ST;
    int k2 = s_nk < S2_ST ? s_nk : S2_ST;
    if (threadIdx.x == 0) {
        s_bc = c  ? atomicAdd(&g_cand2_cnt, c)  : 0;
        s_bk = k2 ? atomicAdd(&g_work_cnt, k2) : 0;
    }
    __syncthreads();
    for (int t2 = threadIdx.x; t2 < c; t2 += 256) {
        int pos = s_bc + t2;
        if (pos < CAND2_CAP) g_cand2[pos] = st_c[t2];
    }
    for (int t2 = threadIdx.x; t2 < k2; t2 += 256)
        g_work[s_bk + t2] = st_k[t2];

    // last block: exact resolve of remaining 42 bits (warp 0)
    __shared__ int s_last;
    __shared__ unsigned long long s_cand[SM_CAND];
    __threadfence();
    if (threadIdx.x == 0)
        s_last = (atomicAdd(&g_done_s2, 1) == (int)gridDim.x - 1);
    __syncthreads();
    if (!s_last) return;

    int c2 = g_cand2_cnt;
    if (c2 > CAND2_CAP) c2 = CAND2_CAP;
    bool in_sm = (c2 <= SM_CAND);
    if (in_sm)
        for (int i = threadIdx.x; i < c2; i += 256) s_cand[i] = g_cand2[i];
    __syncthreads();
    if (threadIdx.x >= 32) return;

    int lane = threadIdx.x;
    unsigned long long F =
        (((unsigned long long)g_d1) << 11) | (unsigned long long)g_d2;
    long long Kr = g_Krem2;
    for (int b = 41; b >= 0; b--) {
        int local = 0;
        for (int i = lane; i < c2; i += 32) {
            unsigned long long k3 = in_sm ? s_cand[i] : g_cand2[i];
            if ((k3 >> (b + 1)) == F && ((k3 >> b) & 1ull)) local++;
        }
        int c1 = __reduce_add_sync(0xffffffffu, local);
        if (c1 >= Kr) F = (F << 1) | 1ull;
        else { Kr -= c1; F <<= 1; }
    }
    for (int i = lane; i < c2; i += 32) {
        unsigned long long k3 = in_sm ? s_cand[i] : g_cand2[i];
        if (k3 >= F) {
            int r = (int)(~(unsigned)(k3 & 0xFFFFFFFFull));
            if (g_conf[r] == 0) {
                int pos = atomicAdd(&g_work_cnt, 1);
                g_work[pos] = r << 8;
            }
        }
    }
}

// ---------------- K5: CE over worklist + output + state reset ----------------
__global__ void __launch_bounds__(256)
k_ce(const float* __restrict__ conf_data, float* __restrict__ out) {
    const float NINF = __int_as_float(0xff800000);
    const int lane = threadIdx.x & 31;
    const int wid  = (blockIdx.x * blockDim.x + threadIdx.x) >> 5;
    const int nw   = (gridDim.x * blockDim.x) >> 5;
    int cnt = g_work_cnt;
    float lce = 0.f;

    // early blocks reset histograms + gt_best for the NEXT replay
    {
        int t = blockIdx.x * 256 + threadIdx.x;
        if (t < 2048) { g_hist0[t] = 0; g_hist1[t] = 0; }
        if (t >= 2048 && t < 2048 + B_ * N_)
            g_gt_best[t - 2048] = 0x00000000FFFFFFFFull;
    }

    for (int i = wid; i < cnt; i += nw) {
        int item = g_work[i];
        int r  = item >> 8;
        int ct = item & 255;
        const float* row = conf_data + (size_t)r * C_;
        float x0 = row[lane];
        float x1 = row[lane + 32];
        float x2 = (lane < 17) ? row[lane + 64] : NINF;
        float m = fmaxf(x0, fmaxf(x1, x2));
        #pragma unroll
        for (int o = 16; o; o >>= 1)
            m = fmaxf(m, __shfl_xor_sync(0xffffffffu, m, o));
        float s = expf(x0 - m) + expf(x1 - m) + ((lane < 17) ? expf(x2 - m) : 0.f);
        #pragma unroll
        for (int o = 16; o; o >>= 1) s += __shfl_xor_sync(0xffffffffu, s, o);
        float tv = NINF;
        if (lane == ct)                   tv = x0;
        if (lane + 32 == ct)              tv = x1;
        if (lane < 17 && lane + 64 == ct) tv = x2;
        #pragma unroll
        for (int o = 16; o; o >>= 1)
            tv = fmaxf(tv, __shfl_xor_sync(0xffffffffu, tv, o));
        if (lane == 0) lce += (m + logf(s)) - tv;
    }

    #pragma unroll
    for (int o = 16; o; o >>= 1) lce += __shfl_xor_sync(0xffffffffu, lce, o);
    __shared__ float sf[8];
    int w = threadIdx.x >> 5;
    if (lane == 0) sf[w] = lce;
    __syncthreads();
    if (threadIdx.x == 0) {
        float a = 0.f;
        #pragma unroll
        for (int i = 0; i < 8; i++) a += sf[i];
        if (a != 0.f) atomicAdd(&g_ce_sum, a);
        __threadfence();
        int done = atomicAdd(&g_done_ce, 1);
        if (done == (int)gridDim.x - 1) {
            int np = g_num_pos; if (np < 1) np = 1;
            int kp = cnt;       if (kp < 1) kp = 1;
            out[0] = g_sl1    / (float)np;
            out[1] = g_ce_sum / (float)kp;
            // ---- reset remaining state for next replay ----
            g_sl1 = 0.f; g_ce_sum = 0.f;
            g_work_cnt = 0; g_cand_cnt = 0; g_cand2_cnt = 0;
            g_num_pos = 0; g_K = 0;
            g_done_match = 0; g_done_tail = 0; g_done_s1 = 0;
            g_done_s2 = 0; g_done_ce = 0;
            __threadfence();
        }
    }
}

// ---------------- host -------------------------------------------------------
extern "C" void kernel_launch(void* const* d_in, const int* in_sizes, int n_in,
                              void* d_out, int out_size) {
    const float* loc = nullptr;
    const float* conf = nullptr;
    const float* priors = nullptr;
    const float* gtb = nullptr;
    const int*   gtl = nullptr;
    for (int i = 0; i < n_in; i++) {
        long long s = in_sizes[i];
        if      (s == (long long)B_ * P_ * C_) conf   = (const float*)d_in[i];
        else if (s == (long long)B_ * P_ * 4)  loc    = (const float*)d_in[i];
        else if (s == (long long)P_ * 4)       priors = (const float*)d_in[i];
        else if (s == (long long)B_ * N_ * 4)  gtb    = (const float*)d_in[i];
        else if (s == (long long)B_ * N_)      gtl    = (const int*)d_in[i];
    }
    float* out = (float*)d_out;

    // capture-safe stream fork: k_match (side) overlaps k_max (main)
    static cudaStream_t s_side = nullptr;
    static cudaEvent_t  e_fork = nullptr, e_join = nullptr;
    if (!s_side) {
        cudaStreamCreateWithFlags(&s_side, cudaStreamNonBlocking);
        cudaEventCreateWithFlags(&e_fork, cudaEventDisableTiming);
        cudaEventCreateWithFlags(&e_join, cudaEventDisableTiming);
    }

    cudaEventRecord(e_fork, 0);
    cudaStreamWaitEvent(s_side, e_fork, 0);
    k_match<<<dim3((P_ + 255) / 256, B_), 256, 0, s_side>>>(priors, gtb);
    cudaEventRecord(e_join, s_side);

    k_max<<<1776, 256>>>(conf);          // concurrent with k_match

    cudaStreamWaitEvent(0, e_join, 0);   // join before tail
    k_tail<<<904, 256>>>(loc, priors, gtb, gtl);
    k_scan1<<<452, 256>>>();
    k_scan2<<<592, 256>>>();
    k_ce<<<464, 256>>>(conf, out);
}